// round 5
// baseline (speedup 1.0000x reference)
#include <cuda_runtime.h>
#include <cuda_bf16.h>
#include <cstdint>

// DynamicSparseAttention — sm_103a, round 5.
// top-k indices provably [0..15]; projections re-associated through 16-slot
// attention. All big GEMMs on HMMA bf16 3-term hi/lo split. This round:
// softmax fused into attn epilogue (CTA n-tile = 4 whole heads), kv on HMMA.

#define Bn   4
#define Tn   1024
#define Cn   1024
#define Hn   16
#define HDn  64
#define KSn  16
#define HKn  256
#define LDT  40          // smem row stride in bf16 (80B) -> conflict-free ldmatrix

typedef __nv_bfloat16 bf16;

// ---- scratch (static device globals; no allocation allowed) ----
__device__ float g_kvp [8*64*2048];        // kv split-K partials
__device__ bf16  g_KQh [Bn*HKn*Cn];        // KQ hi plane (scale 1/8 folded)
__device__ bf16  g_KQl [Bn*HKn*Cn];
__device__ bf16  g_VPTh[Bn*Cn*HKn];        // VP^T [b][j][hk] hi
__device__ bf16  g_VPTl[Bn*Cn*HKn];
__device__ bf16  g_wh  [Bn*Tn*HKn];        // softmax weights hi
__device__ bf16  g_wl  [Bn*Tn*HKn];

// ---- helpers ----
__device__ __forceinline__ uint32_t sptr(const void* p) {
    return (uint32_t)__cvta_generic_to_shared(p);
}
__device__ __forceinline__ void ldsm4(uint32_t* r, uint32_t addr) {
    asm volatile("ldmatrix.sync.aligned.m8n8.x4.shared.b16 {%0,%1,%2,%3}, [%4];"
        : "=r"(r[0]), "=r"(r[1]), "=r"(r[2]), "=r"(r[3]) : "r"(addr));
}
__device__ __forceinline__ void mma16816(float* d, const uint32_t* a, const uint32_t* b) {
    asm volatile("mma.sync.aligned.m16n8k16.row.col.f32.bf16.bf16.f32 "
        "{%0,%1,%2,%3}, {%4,%5,%6,%7}, {%8,%9}, {%0,%1,%2,%3};"
        : "+f"(d[0]), "+f"(d[1]), "+f"(d[2]), "+f"(d[3])
        : "r"(a[0]), "r"(a[1]), "r"(a[2]), "r"(a[3]), "r"(b[0]), "r"(b[1]));
}
__device__ __forceinline__ uint32_t pk2(bf16 a, bf16 b) {
    __nv_bfloat162 t; t.x = a; t.y = b;
    return *reinterpret_cast<uint32_t*>(&t);
}
__device__ __forceinline__ void split2(float v, bf16& h, bf16& l) {
    h = __float2bfloat16_rn(v);
    l = __float2bfloat16_rn(v - __bfloat162float(h));
}

// ---------------------------------------------------------------------------
// K1: kv partials via HMMA. CTA tile 64(m=b,slot) x 128(n of 2048), k-chunk 32,
// split-K x8 (128 k each). grid (16 n, 8 ks), 256 thr (8 warps, 2m x 4n).
// Inline fp32 -> hi/lo bf16 split of x and W_attn during tile load.
// ---------------------------------------------------------------------------
__global__ __launch_bounds__(256,2) void kv_mma(const float* __restrict__ x,
                                                const float* __restrict__ Wa) {
    __shared__ bf16 sm[384*LDT];               // Ah|Al (64) | Bh|Bl (128)
    bf16* Ah = sm;
    bf16* Bh = sm + 128*LDT;
    const int tid = threadIdx.x;
    const int nt  = blockIdx.x;                // 0..15
    const int ks  = blockIdx.y;                // 0..7
    const int lane = tid & 31, wid = tid >> 5;
    const int mBase = (wid & 1) * 32, nBase = (wid >> 1) * 32;

    const int aR = (lane & 7) + ((lane >> 3) & 1)*8;
    const int aC = (lane >> 4)*8;
    const int bR = (lane & 7) + (lane >> 4)*8;
    const int bC = ((lane >> 3) & 1)*8;

    float acc[2][4][4];
#pragma unroll
    for (int mb = 0; mb < 2; ++mb)
#pragma unroll
        for (int nb = 0; nb < 4; ++nb)
#pragma unroll
            for (int q = 0; q < 4; ++q) acc[mb][nb][q] = 0.f;

    for (int k0 = ks*128; k0 < ks*128 + 128; k0 += 32) {
#pragma unroll
        for (int p = 0; p < 2; ++p) {          // A: x rows (b,slot)
            const int idx = tid + p*256;
            const int row = idx >> 3, kq = (idx & 7) * 4;
            const int b = row >> 4, s = row & 15;
            float4 v = *(const float4*)&x[(b*Tn + s)*Cn + k0 + kq];
            bf16 hx,lx,hy,ly,hz,lz,hw,lw;
            split2(v.x,hx,lx); split2(v.y,hy,ly);
            split2(v.z,hz,lz); split2(v.w,hw,lw);
            *(uint2*)&Ah[row*LDT + kq]          = make_uint2(pk2(hx,hy), pk2(hz,hw));
            *(uint2*)&Ah[64*LDT + row*LDT + kq] = make_uint2(pk2(lx,ly), pk2(lz,lw));
        }
#pragma unroll
        for (int p = 0; p < 4; ++p) {          // B: W_attn kv rows
            const int idx = tid + p*256;
            const int row = idx >> 3, kq = (idx & 7) * 4;
            float4 v = *(const float4*)&Wa[(Cn + nt*128 + row)*Cn + k0 + kq];
            bf16 hx,lx,hy,ly,hz,lz,hw,lw;
            split2(v.x,hx,lx); split2(v.y,hy,ly);
            split2(v.z,hz,lz); split2(v.w,hw,lw);
            *(uint2*)&Bh[row*LDT + kq]           = make_uint2(pk2(hx,hy), pk2(hz,hw));
            *(uint2*)&Bh[128*LDT + row*LDT + kq] = make_uint2(pk2(lx,ly), pk2(lz,lw));
        }
        __syncthreads();
#pragma unroll
        for (int kk = 0; kk < 32; kk += 16) {
            uint32_t ah[2][4], al[2][4], bh2[2][4], bl2[2][4];
#pragma unroll
            for (int mb = 0; mb < 2; ++mb) {
                uint32_t ad = sptr(&Ah[(mBase + mb*16 + aR)*LDT + kk + aC]);
                ldsm4(ah[mb], ad);
                ldsm4(al[mb], ad + 64*LDT*2);
            }
#pragma unroll
            for (int q = 0; q < 2; ++q) {
                uint32_t bd = sptr(&Bh[(nBase + q*16 + bR)*LDT + kk + bC]);
                ldsm4(bh2[q], bd);
                ldsm4(bl2[q], bd + 128*LDT*2);
            }
#pragma unroll
            for (int mb = 0; mb < 2; ++mb)
#pragma unroll
                for (int nb = 0; nb < 4; ++nb) {
                    const uint32_t* bhp = &bh2[nb>>1][(nb&1)*2];
                    const uint32_t* blp = &bl2[nb>>1][(nb&1)*2];
                    mma16816(acc[mb][nb], ah[mb], bhp);
                    mma16816(acc[mb][nb], ah[mb], blp);
                    mma16816(acc[mb][nb], al[mb], bhp);
                }
        }
        __syncthreads();
    }
    const int g = lane >> 2, c2 = (lane & 3) * 2;
#pragma unroll
    for (int mb = 0; mb < 2; ++mb)
#pragma unroll
        for (int nb = 0; nb < 4; ++nb) {
            const int row = mBase + mb*16 + g;
            const int col = nt*128 + nBase + nb*8 + c2;
            *(float2*)&g_kvp[(ks*64 + row)*2048 + col] =
                make_float2(acc[mb][nb][0], acc[mb][nb][1]);
            *(float2*)&g_kvp[(ks*64 + row + 8)*2048 + col] =
                make_float2(acc[mb][nb][2], acc[mb][nb][3]);
        }
}

// ---------------------------------------------------------------------------
// K2: merged KQ / VP^T, reducing the 8 kv partials inline.
//   z=0: KQ[b,h,s,c] = 0.125*sum_d Wq[h*64+d,c]*k[b,s,h*64+d] -> bf16 planes
//   z=1: VP[b,h,s,j] = sum_d v[b,s,h*64+d]*Wp[j,h*64+d] -> VPT[b][j][hk] planes
// ---------------------------------------------------------------------------
__global__ __launch_bounds__(256) void kqvp_kernel(const float* __restrict__ Wa,
                                                   const float* __restrict__ Wp) {
    __shared__ float smem[12288];                    // 48KB
    float (*Ws)[128] = (float(*)[128])smem;          // [d][c or j]
    float (*ts)[64]  = (float(*)[64])(smem + 8192);  // [d][r]
    const int ct  = blockIdx.x;    // 0..7
    const int h   = blockIdx.y;    // 0..15
    const int z   = blockIdx.z;    // 0..1
    const int tid = threadIdx.x;
    const int vcol = (z == 0) ? h*HDn : 1024 + h*HDn;

    if (z == 0) {
#pragma unroll
        for (int p = 0; p < 8; ++p) {
            const int idx = tid + p*256;
            const int d   = idx >> 5;
            const int f4  = (idx & 31) << 2;
            float4 v = *(const float4*)&Wa[(h*HDn + d)*Cn + ct*128 + f4];
            *(float4*)&Ws[d][f4] = v;
        }
    } else {
#pragma unroll
        for (int p = 0; p < 8; ++p) {
            const int idx = tid + p*256;
            const int j   = idx >> 4;
            const int f4  = (idx & 15) << 2;
            float4 v = *(const float4*)&Wp[(ct*128 + j)*Cn + h*HDn + f4];
            Ws[f4+0][j] = v.x; Ws[f4+1][j] = v.y;
            Ws[f4+2][j] = v.z; Ws[f4+3][j] = v.w;
        }
    }
#pragma unroll
    for (int p = 0; p < 4; ++p) {
        const int idx = tid + p*256;
        const int r   = idx >> 4;
        const int f4  = (idx & 15) << 2;
        float4 s = make_float4(0.f, 0.f, 0.f, 0.f);
#pragma unroll
        for (int ksp = 0; ksp < 8; ++ksp) {
            float4 v = *(const float4*)&g_kvp[(ksp*64 + r)*2048 + vcol + f4];
            s.x += v.x; s.y += v.y; s.z += v.z; s.w += v.w;
        }
        ts[f4+0][r] = s.x; ts[f4+1][r] = s.y;
        ts[f4+2][r] = s.z; ts[f4+3][r] = s.w;
    }
    __syncthreads();

    const int r0 = (tid >> 4) << 2;
    const int c0 = (tid & 15) << 3;
    float acc[4][8];
#pragma unroll
    for (int i = 0; i < 4; ++i)
#pragma unroll
        for (int j = 0; j < 8; ++j) acc[i][j] = 0.f;

#pragma unroll 8
    for (int d = 0; d < 64; ++d) {
        float4 a  = *(const float4*)&ts[d][r0];
        float4 b0 = *(const float4*)&Ws[d][c0];
        float4 b1 = *(const float4*)&Ws[d][c0+4];
        const float av[4] = {a.x, a.y, a.z, a.w};
        const float bv[8] = {b0.x,b0.y,b0.z,b0.w,b1.x,b1.y,b1.z,b1.w};
#pragma unroll
        for (int i = 0; i < 4; ++i)
#pragma unroll
            for (int j = 0; j < 8; ++j) acc[i][j] += av[i]*bv[j];
    }

    if (z == 0) {
#pragma unroll
        for (int i = 0; i < 4; ++i) {
            const int r = r0 + i, b = r >> 4, s = r & 15;
            const int base = (b*HKn + h*KSn + s)*Cn + ct*128 + c0;
            bf16 hi[8], lo[8];
#pragma unroll
            for (int j = 0; j < 8; ++j) split2(acc[i][j] * 0.125f, hi[j], lo[j]);
            *(uint4*)&g_KQh[base] = make_uint4(pk2(hi[0],hi[1]), pk2(hi[2],hi[3]),
                                               pk2(hi[4],hi[5]), pk2(hi[6],hi[7]));
            *(uint4*)&g_KQl[base] = make_uint4(pk2(lo[0],lo[1]), pk2(lo[2],lo[3]),
                                               pk2(lo[4],lo[5]), pk2(lo[6],lo[7]));
        }
    } else {
        __syncthreads();
        float* tp = smem;                       // [r 64][129]
#pragma unroll
        for (int i = 0; i < 4; ++i)
#pragma unroll
            for (int j = 0; j < 8; ++j)
                tp[(r0+i)*129 + c0 + j] = acc[i][j];
        __syncthreads();
#pragma unroll
        for (int p = 0; p < 2; ++p) {
            const int run = tid + p*256;
            const int bb  = run >> 7;
            const int j   = run & 127;
            bf16 hi[16], lo[16];
#pragma unroll
            for (int s = 0; s < 16; ++s)
                split2(tp[(bb*16 + s)*129 + j], hi[s], lo[s]);
            const int dst = (bb*Cn + ct*128 + j)*HKn + h*KSn;
            *(uint4*)&g_VPTh[dst]   = make_uint4(pk2(hi[0],hi[1]), pk2(hi[2],hi[3]),
                                                 pk2(hi[4],hi[5]), pk2(hi[6],hi[7]));
            *(uint4*)&g_VPTh[dst+8] = make_uint4(pk2(hi[8],hi[9]), pk2(hi[10],hi[11]),
                                                 pk2(hi[12],hi[13]), pk2(hi[14],hi[15]));
            *(uint4*)&g_VPTl[dst]   = make_uint4(pk2(lo[0],lo[1]), pk2(lo[2],lo[3]),
                                                 pk2(lo[4],lo[5]), pk2(lo[6],lo[7]));
            *(uint4*)&g_VPTl[dst+8] = make_uint4(pk2(lo[8],lo[9]), pk2(lo[10],lo[11]),
                                                 pk2(lo[12],lo[13]), pk2(lo[14],lo[15]));
        }
    }
}

// ---------------------------------------------------------------------------
// K3: logits = x @ KQ^T with FUSED softmax. CTA tile 64(t) x 64(hk = 4 whole
// heads), full K=1024. grid (4 n, 16 m, 4 b) = 256 CTAs, 128 thr (4 warps
// 2m x 2n, warp 32x32). Epilogue: logits -> smem -> masked softmax -> w planes.
// ---------------------------------------------------------------------------
__global__ __launch_bounds__(128) void attn_fused(const float* __restrict__ x) {
    __shared__ bf16 sm[256*LDT];               // Ah|Al (64) | Bh|Bl (64), 20.5KB
    bf16* Ah = sm;
    bf16* Bh = sm + 128*LDT;
    const int tid  = threadIdx.x;
    const int nIdx = blockIdx.x;               // 0..3
    const int mIdx = blockIdx.y;               // 0..15
    const int b    = blockIdx.z;
    const int trow0 = b*Tn + mIdx*64;
    const int n0 = nIdx*64;
    const int lane = tid & 31, wid = tid >> 5;
    const int mBase = (wid & 1) * 32, nBase = (wid >> 1) * 32;

    const int aR = (lane & 7) + ((lane >> 3) & 1)*8;
    const int aC = (lane >> 4)*8;
    const int bR = (lane & 7) + (lane >> 4)*8;
    const int bC = ((lane >> 3) & 1)*8;

    float acc[2][4][4];
#pragma unroll
    for (int mb = 0; mb < 2; ++mb)
#pragma unroll
        for (int nb = 0; nb < 4; ++nb)
#pragma unroll
            for (int q = 0; q < 4; ++q) acc[mb][nb][q] = 0.f;

    for (int k0 = 0; k0 < Cn; k0 += 32) {
#pragma unroll
        for (int p = 0; p < 4; ++p) {          // A: x fp32 -> hi/lo inline
            const int idx = tid + p*128;
            const int row = idx >> 3, kq = (idx & 7) * 4;
            float4 v = *(const float4*)&x[(trow0+row)*Cn + k0 + kq];
            bf16 hx,lx,hy,ly,hz,lz,hw,lw;
            split2(v.x,hx,lx); split2(v.y,hy,ly);
            split2(v.z,hz,lz); split2(v.w,hw,lw);
            *(uint2*)&Ah[row*LDT + kq]          = make_uint2(pk2(hx,hy), pk2(hz,hw));
            *(uint2*)&Ah[64*LDT + row*LDT + kq] = make_uint2(pk2(lx,ly), pk2(lz,lw));
        }
#pragma unroll
        for (int p = 0; p < 2; ++p) {          // B: KQ planes (bf16 direct)
            const int idx = tid + p*128;
            const int row = idx >> 2, kq = (idx & 3) * 8;
            const int gi = (b*HKn + n0 + row)*Cn + k0 + kq;
            *(uint4*)&Bh[row*LDT + kq]          = *(const uint4*)&g_KQh[gi];
            *(uint4*)&Bh[64*LDT + row*LDT + kq] = *(const uint4*)&g_KQl[gi];
        }
        __syncthreads();
#pragma unroll
        for (int kk = 0; kk < 32; kk += 16) {
            uint32_t ah[2][4], al[2][4], bh2[2][4], bl2[2][4];
#pragma unroll
            for (int mb = 0; mb < 2; ++mb) {
                uint32_t ad = sptr(&Ah[(mBase + mb*16 + aR)*LDT + kk + aC]);
                ldsm4(ah[mb], ad);
                ldsm4(al[mb], ad + 64*LDT*2);
            }
#pragma unroll
            for (int q = 0; q < 2; ++q) {
                uint32_t bd = sptr(&Bh[(nBase + q*16 + bR)*LDT + kk + bC]);
                ldsm4(bh2[q], bd);
                ldsm4(bl2[q], bd + 64*LDT*2);
            }
#pragma unroll
            for (int mb = 0; mb < 2; ++mb)
#pragma unroll
                for (int nb = 0; nb < 4; ++nb) {
                    const uint32_t* bhp = &bh2[nb>>1][(nb&1)*2];
                    const uint32_t* blp = &bl2[nb>>1][(nb&1)*2];
                    mma16816(acc[mb][nb], ah[mb], bhp);
                    mma16816(acc[mb][nb], ah[mb], blp);
                    mma16816(acc[mb][nb], al[mb], bhp);
                }
        }
        __syncthreads();
    }

    // stage logits (64 x 64, stride 68) in smem, reusing GEMM buffers
    float* lg = (float*)sm;
    const int g = lane >> 2, c2 = (lane & 3) * 2;
#pragma unroll
    for (int mb = 0; mb < 2; ++mb)
#pragma unroll
        for (int nb = 0; nb < 4; ++nb) {
            const int r0 = mBase + mb*16 + g;
            const int col = nBase + nb*8 + c2;
            *(float2*)&lg[r0*68 + col] =
                make_float2(acc[mb][nb][0], acc[mb][nb][1]);
            *(float2*)&lg[(r0+8)*68 + col] =
                make_float2(acc[mb][nb][2], acc[mb][nb][3]);
        }
    __syncthreads();

    // masked softmax: 64 rows x 4 heads = 256 groups, 2 per thread
#pragma unroll
    for (int p = 0; p < 2; ++p) {
        const int g2 = tid + p*128;
        const int tl = g2 >> 2;                // 0..63
        const int hl = g2 & 3;                 // head local
        const int tb = mIdx*64 + tl;           // t within batch
        const int cnt = (tb + 1 < KSn) ? tb + 1 : KSn;
        const float* rowp = &lg[tl*68 + hl*16];
        float m = -3.0e38f;
#pragma unroll
        for (int s = 0; s < KSn; ++s) if (s < cnt) m = fmaxf(m, rowp[s]);
        float e[KSn]; float sum = 0.f;
#pragma unroll
        for (int s = 0; s < KSn; ++s) {
            float v = (s < cnt) ? expf(rowp[s] - m) : 0.f;
            e[s] = v; sum += v;
        }
        const float inv = 1.f / sum;
        bf16 hi[16], lo[16];
#pragma unroll
        for (int s = 0; s < KSn; ++s) split2(e[s]*inv, hi[s], lo[s]);
        const int base = (b*Tn + tb)*HKn + n0 + hl*16;
        *(uint4*)&g_wh[base]   = make_uint4(pk2(hi[0],hi[1]), pk2(hi[2],hi[3]),
                                            pk2(hi[4],hi[5]), pk2(hi[6],hi[7]));
        *(uint4*)&g_wh[base+8] = make_uint4(pk2(hi[8],hi[9]), pk2(hi[10],hi[11]),
                                            pk2(hi[12],hi[13]), pk2(hi[14],hi[15]));
        *(uint4*)&g_wl[base]   = make_uint4(pk2(lo[0],lo[1]), pk2(lo[2],lo[3]),
                                            pk2(lo[4],lo[5]), pk2(lo[6],lo[7]));
        *(uint4*)&g_wl[base+8] = make_uint4(pk2(lo[8],lo[9]), pk2(lo[10],lo[11]),
                                            pk2(lo[12],lo[13]), pk2(lo[14],lo[15]));
    }
}

// ---------------------------------------------------------------------------
// K4: out = w @ VP via HMMA. CTA tile 128(t) x 64(j), K=256.
// grid (16 n, 8 m, 4 b), 256 thr (8 warps, 4m x 2n).
// ---------------------------------------------------------------------------
__global__ __launch_bounds__(256,2) void out_mma(float* __restrict__ out) {
    __shared__ bf16 sm[384*LDT];
    bf16* Ah = sm;
    bf16* Bh = sm + 256*LDT;
    const int tid  = threadIdx.x;
    const int nIdx = blockIdx.x;               // 0..15
    const int mIdx = blockIdx.y;               // 0..7
    const int b    = blockIdx.z;
    const int trow0 = b*Tn + mIdx*128;
    const int j0 = nIdx*64;
    const int lane = tid & 31, wid = tid >> 5;
    const int mBase = (wid & 3) * 32, nBase = (wid >> 2) * 32;

    const int aR = (lane & 7) + ((lane >> 3) & 1)*8;
    const int aC = (lane >> 4)*8;
    const int bR = (lane & 7) + (lane >> 4)*8;
    const int bC = ((lane >> 3) & 1)*8;

    float acc[2][4][4];
#pragma unroll
    for (int mb = 0; mb < 2; ++mb)
#pragma unroll
        for (int nb = 0; nb < 4; ++nb)
#pragma unroll
            for (int q = 0; q < 4; ++q) acc[mb][nb][q] = 0.f;

    for (int k0 = 0; k0 < HKn; k0 += 32) {
#pragma unroll
        for (int p = 0; p < 2; ++p) {          // A: w planes
            const int idx = tid + p*256;
            const int row = idx >> 2, kq = (idx & 3) * 8;
            const int gi = (trow0+row)*HKn + k0 + kq;
            *(uint4*)&Ah[row*LDT + kq]           = *(const uint4*)&g_wh[gi];
            *(uint4*)&Ah[128*LDT + row*LDT + kq] = *(const uint4*)&g_wl[gi];
        }
        {                                      // B: VPT planes
            const int row = tid >> 2, kq = (tid & 3) * 8;
            const int gi = (b*Cn + j0 + row)*HKn + k0 + kq;
            *(uint4*)&Bh[row*LDT + kq]          = *(const uint4*)&g_VPTh[gi];
            *(uint4*)&Bh[64*LDT + row*LDT + kq] = *(const uint4*)&g_VPTl[gi];
        }
        __syncthreads();
#pragma unroll
        for (int kk = 0; kk < 32; kk += 16) {
            uint32_t ah[2][4], al[2][4], bh2[2][4], bl2[2][4];
#pragma unroll
            for (int mb = 0; mb < 2; ++mb) {
                uint32_t ad = sptr(&Ah[(mBase + mb*16 + aR)*LDT + kk + aC]);
                ldsm4(ah[mb], ad);
                ldsm4(al[mb], ad + 128*LDT*2);
            }
#pragma unroll
            for (int q = 0; q < 2; ++q) {
                uint32_t bd = sptr(&Bh[(nBase + q*16 + bR)*LDT + kk + bC]);
                ldsm4(bh2[q], bd);
                ldsm4(bl2[q], bd + 64*LDT*2);
            }
#pragma unroll
            for (int mb = 0; mb < 2; ++mb)
#pragma unroll
                for (int nb = 0; nb < 4; ++nb) {
                    const uint32_t* bhp = &bh2[nb>>1][(nb&1)*2];
                    const uint32_t* blp = &bl2[nb>>1][(nb&1)*2];
                    mma16816(acc[mb][nb], ah[mb], bhp);
                    mma16816(acc[mb][nb], ah[mb], blp);
                    mma16816(acc[mb][nb], al[mb], bhp);
                }
        }
        __syncthreads();
    }
    const int g = lane >> 2, c2 = (lane & 3) * 2;
#pragma unroll
    for (int mb = 0; mb < 2; ++mb)
#pragma unroll
        for (int nb = 0; nb < 4; ++nb) {
            const int row = trow0 + mBase + mb*16 + g;
            const int col = j0 + nBase + nb*8 + c2;
            *(float2*)&out[row*Cn + col] =
                make_float2(acc[mb][nb][0], acc[mb][nb][1]);
            *(float2*)&out[(row + 8)*Cn + col] =
                make_float2(acc[mb][nb][2], acc[mb][nb][3]);
        }
}

// ---------------------------------------------------------------------------
extern "C" void kernel_launch(void* const* d_in, const int* in_sizes, int n_in,
                              void* d_out, int out_size) {
    const float* x  = (const float*)d_in[0];
    const float* Wa = (const float*)d_in[1];
    const float* Wp = (const float*)d_in[2];
    float* out = (float*)d_out;

    kv_mma     <<<dim3(16, 8),    256>>>(x, Wa);
    kqvp_kernel<<<dim3(8, 16, 2), 256>>>(Wa, Wp);
    attn_fused <<<dim3(4, 16, 4), 128>>>(x);
    out_mma    <<<dim3(16, 8, 4), 256>>>(out);
}

// round 7
// speedup vs baseline: 1.0602x; 1.0602x over previous
#include <cuda_runtime.h>
#include <cuda_bf16.h>
#include <cstdint>

// DynamicSparseAttention — sm_103a, round 6.
// top-k indices provably [0..15]; projections re-associated through 16-slot
// attention. HMMA bf16 3-term hi/lo split everywhere. This round: 2-stage
// cp.async pipelines in the two big GEMMs + pre-split x planes + bigger grids.

#define Bn   4
#define Tn   1024
#define Cn   1024
#define Hn   16
#define HDn  64
#define KSn  16
#define HKn  256
#define LDT  40          // smem row stride in bf16 (80B) -> conflict-free ldmatrix

typedef __nv_bfloat16 bf16;

// ---- scratch (static device globals; no allocation allowed) ----
__device__ float g_kvp [8*64*2048];        // kv split-K partials
__device__ bf16  g_xh  [Bn*Tn*Cn];         // x hi plane
__device__ bf16  g_xl  [Bn*Tn*Cn];         // x lo plane
__device__ bf16  g_KQh [Bn*HKn*Cn];        // KQ hi plane (scale 1/8 folded)
__device__ bf16  g_KQl [Bn*HKn*Cn];
__device__ bf16  g_VPTh[Bn*Cn*HKn];        // VP^T [b][j][hk] hi
__device__ bf16  g_VPTl[Bn*Cn*HKn];
__device__ bf16  g_wh  [Bn*Tn*HKn];        // softmax weights hi
__device__ bf16  g_wl  [Bn*Tn*HKn];

// ---- helpers ----
__device__ __forceinline__ uint32_t sptr(const void* p) {
    return (uint32_t)__cvta_generic_to_shared(p);
}
__device__ __forceinline__ void ldsm4(uint32_t* r, uint32_t addr) {
    asm volatile("ldmatrix.sync.aligned.m8n8.x4.shared.b16 {%0,%1,%2,%3}, [%4];"
        : "=r"(r[0]), "=r"(r[1]), "=r"(r[2]), "=r"(r[3]) : "r"(addr));
}
__device__ __forceinline__ void mma16816(float* d, const uint32_t* a, const uint32_t* b) {
    asm volatile("mma.sync.aligned.m16n8k16.row.col.f32.bf16.bf16.f32 "
        "{%0,%1,%2,%3}, {%4,%5,%6,%7}, {%8,%9}, {%0,%1,%2,%3};"
        : "+f"(d[0]), "+f"(d[1]), "+f"(d[2]), "+f"(d[3])
        : "r"(a[0]), "r"(a[1]), "r"(a[2]), "r"(a[3]), "r"(b[0]), "r"(b[1]));
}
__device__ __forceinline__ uint32_t pk2(bf16 a, bf16 b) {
    __nv_bfloat162 t; t.x = a; t.y = b;
    return *reinterpret_cast<uint32_t*>(&t);
}
__device__ __forceinline__ void split2(float v, bf16& h, bf16& l) {
    h = __float2bfloat16_rn(v);
    l = __float2bfloat16_rn(v - __bfloat162float(h));
}
__device__ __forceinline__ void cpa16(uint32_t dst, const void* src) {
    asm volatile("cp.async.cg.shared.global [%0], [%1], 16;" :: "r"(dst), "l"(src));
}
#define CP_COMMIT() asm volatile("cp.async.commit_group;")

// ---------------------------------------------------------------------------
// K0: split x fp32 -> bf16 hi/lo planes.  grid 4096 x 256, 4 floats/thread.
// ---------------------------------------------------------------------------
__global__ __launch_bounds__(256) void xsplit_kernel(const float* __restrict__ x) {
    const int i = (blockIdx.x*256 + threadIdx.x) * 4;
    float4 v = *(const float4*)&x[i];
    bf16 h0,l0,h1,l1,h2,l2,h3,l3;
    split2(v.x,h0,l0); split2(v.y,h1,l1);
    split2(v.z,h2,l2); split2(v.w,h3,l3);
    *(uint2*)&g_xh[i] = make_uint2(pk2(h0,h1), pk2(h2,h3));
    *(uint2*)&g_xl[i] = make_uint2(pk2(l0,l1), pk2(l2,l3));
}

// ---------------------------------------------------------------------------
// K1: kv partials via HMMA. CTA 64(m) x 128(n of 2048), split-K x8.
// ---------------------------------------------------------------------------
__global__ __launch_bounds__(256,2) void kv_mma(const float* __restrict__ x,
                                                const float* __restrict__ Wa) {
    __shared__ __align__(16) bf16 sm[384*LDT];
    bf16* Ah = sm;
    bf16* Bh = sm + 128*LDT;
    const int tid = threadIdx.x;
    const int nt  = blockIdx.x;
    const int ks  = blockIdx.y;
    const int lane = tid & 31, wid = tid >> 5;
    const int mBase = (wid & 1) * 32, nBase = (wid >> 1) * 32;

    const int aR = (lane & 7) + ((lane >> 3) & 1)*8;
    const int aC = (lane >> 4)*8;
    const int bR = (lane & 7) + (lane >> 4)*8;
    const int bC = ((lane >> 3) & 1)*8;

    float acc[2][4][4];
#pragma unroll
    for (int mb = 0; mb < 2; ++mb)
#pragma unroll
        for (int nb = 0; nb < 4; ++nb)
#pragma unroll
            for (int q = 0; q < 4; ++q) acc[mb][nb][q] = 0.f;

    for (int k0 = ks*128; k0 < ks*128 + 128; k0 += 32) {
#pragma unroll
        for (int p = 0; p < 2; ++p) {
            const int idx = tid + p*256;
            const int row = idx >> 3, kq = (idx & 7) * 4;
            const int b = row >> 4, s = row & 15;
            float4 v = *(const float4*)&x[(b*Tn + s)*Cn + k0 + kq];
            bf16 hx,lx,hy,ly,hz,lz,hw,lw;
            split2(v.x,hx,lx); split2(v.y,hy,ly);
            split2(v.z,hz,lz); split2(v.w,hw,lw);
            *(uint2*)&Ah[row*LDT + kq]          = make_uint2(pk2(hx,hy), pk2(hz,hw));
            *(uint2*)&Ah[64*LDT + row*LDT + kq] = make_uint2(pk2(lx,ly), pk2(lz,lw));
        }
#pragma unroll
        for (int p = 0; p < 4; ++p) {
            const int idx = tid + p*256;
            const int row = idx >> 3, kq = (idx & 7) * 4;
            float4 v = *(const float4*)&Wa[(Cn + nt*128 + row)*Cn + k0 + kq];
            bf16 hx,lx,hy,ly,hz,lz,hw,lw;
            split2(v.x,hx,lx); split2(v.y,hy,ly);
            split2(v.z,hz,lz); split2(v.w,hw,lw);
            *(uint2*)&Bh[row*LDT + kq]           = make_uint2(pk2(hx,hy), pk2(hz,hw));
            *(uint2*)&Bh[128*LDT + row*LDT + kq] = make_uint2(pk2(lx,ly), pk2(lz,lw));
        }
        __syncthreads();
#pragma unroll
        for (int kk = 0; kk < 32; kk += 16) {
            uint32_t ah[2][4], al[2][4], bh2[2][4], bl2[2][4];
#pragma unroll
            for (int mb = 0; mb < 2; ++mb) {
                uint32_t ad = sptr(&Ah[(mBase + mb*16 + aR)*LDT + kk + aC]);
                ldsm4(ah[mb], ad);
                ldsm4(al[mb], ad + 64*LDT*2);
            }
#pragma unroll
            for (int q = 0; q < 2; ++q) {
                uint32_t bd = sptr(&Bh[(nBase + q*16 + bR)*LDT + kk + bC]);
                ldsm4(bh2[q], bd);
                ldsm4(bl2[q], bd + 128*LDT*2);
            }
#pragma unroll
            for (int mb = 0; mb < 2; ++mb)
#pragma unroll
                for (int nb = 0; nb < 4; ++nb) {
                    const uint32_t* bhp = &bh2[nb>>1][(nb&1)*2];
                    const uint32_t* blp = &bl2[nb>>1][(nb&1)*2];
                    mma16816(acc[mb][nb], ah[mb], bhp);
                    mma16816(acc[mb][nb], ah[mb], blp);
                    mma16816(acc[mb][nb], al[mb], bhp);
                }
        }
        __syncthreads();
    }
    const int g = lane >> 2, c2 = (lane & 3) * 2;
#pragma unroll
    for (int mb = 0; mb < 2; ++mb)
#pragma unroll
        for (int nb = 0; nb < 4; ++nb) {
            const int row = mBase + mb*16 + g;
            const int col = nt*128 + nBase + nb*8 + c2;
            *(float2*)&g_kvp[(ks*64 + row)*2048 + col] =
                make_float2(acc[mb][nb][0], acc[mb][nb][1]);
            *(float2*)&g_kvp[(ks*64 + row + 8)*2048 + col] =
                make_float2(acc[mb][nb][2], acc[mb][nb][3]);
        }
}

// ---------------------------------------------------------------------------
// K2: merged KQ / VP^T, reducing 8 kv partials inline (unchanged).
// ---------------------------------------------------------------------------
__global__ __launch_bounds__(256) void kqvp_kernel(const float* __restrict__ Wa,
                                                   const float* __restrict__ Wp) {
    __shared__ float smem[12288];
    float (*Ws)[128] = (float(*)[128])smem;
    float (*ts)[64]  = (float(*)[64])(smem + 8192);
    const int ct  = blockIdx.x;
    const int h   = blockIdx.y;
    const int z   = blockIdx.z;
    const int tid = threadIdx.x;
    const int vcol = (z == 0) ? h*HDn : 1024 + h*HDn;

    if (z == 0) {
#pragma unroll
        for (int p = 0; p < 8; ++p) {
            const int idx = tid + p*256;
            const int d   = idx >> 5;
            const int f4  = (idx & 31) << 2;
            float4 v = *(const float4*)&Wa[(h*HDn + d)*Cn + ct*128 + f4];
            *(float4*)&Ws[d][f4] = v;
        }
    } else {
#pragma unroll
        for (int p = 0; p < 8; ++p) {
            const int idx = tid + p*256;
            const int j   = idx >> 4;
            const int f4  = (idx & 15) << 2;
            float4 v = *(const float4*)&Wp[(ct*128 + j)*Cn + h*HDn + f4];
            Ws[f4+0][j] = v.x; Ws[f4+1][j] = v.y;
            Ws[f4+2][j] = v.z; Ws[f4+3][j] = v.w;
        }
    }
#pragma unroll
    for (int p = 0; p < 4; ++p) {
        const int idx = tid + p*256;
        const int r   = idx >> 4;
        const int f4  = (idx & 15) << 2;
        float4 s = make_float4(0.f, 0.f, 0.f, 0.f);
#pragma unroll
        for (int ksp = 0; ksp < 8; ++ksp) {
            float4 v = *(const float4*)&g_kvp[(ksp*64 + r)*2048 + vcol + f4];
            s.x += v.x; s.y += v.y; s.z += v.z; s.w += v.w;
        }
        ts[f4+0][r] = s.x; ts[f4+1][r] = s.y;
        ts[f4+2][r] = s.z; ts[f4+3][r] = s.w;
    }
    __syncthreads();

    const int r0 = (tid >> 4) << 2;
    const int c0 = (tid & 15) << 3;
    float acc[4][8];
#pragma unroll
    for (int i = 0; i < 4; ++i)
#pragma unroll
        for (int j = 0; j < 8; ++j) acc[i][j] = 0.f;

#pragma unroll 8
    for (int d = 0; d < 64; ++d) {
        float4 a  = *(const float4*)&ts[d][r0];
        float4 b0 = *(const float4*)&Ws[d][c0];
        float4 b1 = *(const float4*)&Ws[d][c0+4];
        const float av[4] = {a.x, a.y, a.z, a.w};
        const float bv[8] = {b0.x,b0.y,b0.z,b0.w,b1.x,b1.y,b1.z,b1.w};
#pragma unroll
        for (int i = 0; i < 4; ++i)
#pragma unroll
            for (int j = 0; j < 8; ++j) acc[i][j] += av[i]*bv[j];
    }

    if (z == 0) {
#pragma unroll
        for (int i = 0; i < 4; ++i) {
            const int r = r0 + i, b = r >> 4, s = r & 15;
            const int base = (b*HKn + h*KSn + s)*Cn + ct*128 + c0;
            bf16 hi[8], lo[8];
#pragma unroll
            for (int j = 0; j < 8; ++j) split2(acc[i][j] * 0.125f, hi[j], lo[j]);
            *(uint4*)&g_KQh[base] = make_uint4(pk2(hi[0],hi[1]), pk2(hi[2],hi[3]),
                                               pk2(hi[4],hi[5]), pk2(hi[6],hi[7]));
            *(uint4*)&g_KQl[base] = make_uint4(pk2(lo[0],lo[1]), pk2(lo[2],lo[3]),
                                               pk2(lo[4],lo[5]), pk2(lo[6],lo[7]));
        }
    } else {
        __syncthreads();
        float* tp = smem;
#pragma unroll
        for (int i = 0; i < 4; ++i)
#pragma unroll
            for (int j = 0; j < 8; ++j)
                tp[(r0+i)*129 + c0 + j] = acc[i][j];
        __syncthreads();
#pragma unroll
        for (int p = 0; p < 2; ++p) {
            const int run = tid + p*256;
            const int bb  = run >> 7;
            const int j   = run & 127;
            bf16 hi[16], lo[16];
#pragma unroll
            for (int s = 0; s < 16; ++s)
                split2(tp[(bb*16 + s)*129 + j], hi[s], lo[s]);
            const int dst = (bb*Cn + ct*128 + j)*HKn + h*KSn;
            *(uint4*)&g_VPTh[dst]   = make_uint4(pk2(hi[0],hi[1]), pk2(hi[2],hi[3]),
                                                 pk2(hi[4],hi[5]), pk2(hi[6],hi[7]));
            *(uint4*)&g_VPTh[dst+8] = make_uint4(pk2(hi[8],hi[9]), pk2(hi[10],hi[11]),
                                                 pk2(hi[12],hi[13]), pk2(hi[14],hi[15]));
            *(uint4*)&g_VPTl[dst]   = make_uint4(pk2(lo[0],lo[1]), pk2(lo[2],lo[3]),
                                                 pk2(lo[4],lo[5]), pk2(lo[6],lo[7]));
            *(uint4*)&g_VPTl[dst+8] = make_uint4(pk2(lo[8],lo[9]), pk2(lo[10],lo[11]),
                                                 pk2(lo[12],lo[13]), pk2(lo[14],lo[15]));
        }
    }
}

// ---------------------------------------------------------------------------
// K3: logits = x @ KQ^T + fused softmax, 2-stage cp.async pipeline.
// CTA tile 32(t) x 64(hk = 4 whole heads), K=1024 in 32-chunks.
// grid (4 n, 32 m, 4 b) = 512 CTAs, 128 thr (4 warps: 2m16 x 2n32).
// ---------------------------------------------------------------------------
#define AT_STG (192*LDT)     // per-stage: A 64 rows (32 hi+32 lo) + B 128 rows

__global__ __launch_bounds__(128) void attn_fused(int dummy) {
    __shared__ __align__(16) bf16 sm[2*AT_STG];   // 30.7KB
    const int tid  = threadIdx.x;
    const int nIdx = blockIdx.x;
    const int mIdx = blockIdx.y;
    const int b    = blockIdx.z;
    const int trow0 = b*Tn + mIdx*32;
    const int n0 = nIdx*64;
    const int lane = tid & 31, wid = tid >> 5;
    const int mBase = (wid & 1) * 16, nBase = (wid >> 1) * 32;

    const int aR = (lane & 7) + ((lane >> 3) & 1)*8;
    const int aC = (lane >> 4)*8;
    const int bR = (lane & 7) + (lane >> 4)*8;
    const int bC = ((lane >> 3) & 1)*8;

    float acc[4][4];
#pragma unroll
    for (int nb = 0; nb < 4; ++nb)
#pragma unroll
        for (int q = 0; q < 4; ++q) acc[nb][q] = 0.f;

    auto loadStage = [&](int s, int k0) {
        bf16* As = sm + s*AT_STG;
        bf16* Bs = As + 64*LDT;
#pragma unroll
        for (int p = 0; p < 2; ++p) {            // A: 64 rows (hi|lo)
            const int idx = tid + p*128;
            const int r = idx >> 2;
            const int row = r & 31, pl = r >> 5;
            const int col = (idx & 3) * 8;
            const bf16* src = (pl ? g_xl : g_xh) + (trow0 + row)*Cn + k0 + col;
            cpa16(sptr(&As[r*LDT + col]), src);
        }
#pragma unroll
        for (int p = 0; p < 4; ++p) {            // B: 128 rows (hi|lo)
            const int idx = tid + p*128;
            const int r = idx >> 2;
            const int n = r & 63, pl = r >> 6;
            const int col = (idx & 3) * 8;
            const bf16* src = (pl ? g_KQl : g_KQh) + (b*HKn + n0 + n)*Cn + k0 + col;
            cpa16(sptr(&Bs[r*LDT + col]), src);
        }
    };

    loadStage(0, 0);
    CP_COMMIT();
    const int nIter = Cn / 32;                   // 32
    for (int it = 0; it < nIter; ++it) {
        bf16* As = sm + (it & 1)*AT_STG;
        bf16* Bs = As + 64*LDT;
        if (it + 1 < nIter) {
            loadStage((it + 1) & 1, (it + 1) * 32);
            CP_COMMIT();
            asm volatile("cp.async.wait_group 1;");
        } else {
            asm volatile("cp.async.wait_group 0;");
        }
        __syncthreads();
#pragma unroll
        for (int kk = 0; kk < 32; kk += 16) {
            uint32_t ah[4], al[4], bh2[2][4], bl2[2][4];
            uint32_t ad = sptr(&As[(mBase + aR)*LDT + kk + aC]);
            ldsm4(ah, ad);
            ldsm4(al, ad + 32*LDT*2);
#pragma unroll
            for (int q = 0; q < 2; ++q) {
                uint32_t bd = sptr(&Bs[(nBase + q*16 + bR)*LDT + kk + bC]);
                ldsm4(bh2[q], bd);
                ldsm4(bl2[q], bd + 64*LDT*2);
            }
#pragma unroll
            for (int nb = 0; nb < 4; ++nb) {
                const uint32_t* bhp = &bh2[nb>>1][(nb&1)*2];
                const uint32_t* blp = &bl2[nb>>1][(nb&1)*2];
                mma16816(acc[nb], ah, bhp);
                mma16816(acc[nb], ah, blp);
                mma16816(acc[nb], al, bhp);
            }
        }
        __syncthreads();
    }

    // stage logits (32 x 64, stride 68) in smem
    float* lg = (float*)sm;
    const int g = lane >> 2, c2 = (lane & 3) * 2;
#pragma unroll
    for (int nb = 0; nb < 4; ++nb) {
        const int r0 = mBase + g;
        const int col = nBase + nb*8 + c2;
        *(float2*)&lg[r0*68 + col]     = make_float2(acc[nb][0], acc[nb][1]);
        *(float2*)&lg[(r0+8)*68 + col] = make_float2(acc[nb][2], acc[nb][3]);
    }
    __syncthreads();

    // masked softmax: 32 rows x 4 heads = 128 groups, 1 per thread
    {
        const int tl = tid >> 2;                 // 0..31
        const int hl = tid & 3;
        const int tb = mIdx*32 + tl;
        const int cnt = (tb + 1 < KSn) ? tb + 1 : KSn;
        const float* rowp = &lg[tl*68 + hl*16];
        float m = -3.0e38f;
#pragma unroll
        for (int s = 0; s < KSn; ++s) if (s < cnt) m = fmaxf(m, rowp[s]);
        float e[KSn]; float sum = 0.f;
#pragma unroll
        for (int s = 0; s < KSn; ++s) {
            float v = (s < cnt) ? expf(rowp[s] - m) : 0.f;
            e[s] = v; sum += v;
        }
        const float inv = 1.f / sum;
        bf16 hi[16], lo[16];
#pragma unroll
        for (int s = 0; s < KSn; ++s) split2(e[s]*inv, hi[s], lo[s]);
        const int base = (b*Tn + tb)*HKn + n0 + hl*16;
        *(uint4*)&g_wh[base]   = make_uint4(pk2(hi[0],hi[1]), pk2(hi[2],hi[3]),
                                            pk2(hi[4],hi[5]), pk2(hi[6],hi[7]));
        *(uint4*)&g_wh[base+8] = make_uint4(pk2(hi[8],hi[9]), pk2(hi[10],hi[11]),
                                            pk2(hi[12],hi[13]), pk2(hi[14],hi[15]));
        *(uint4*)&g_wl[base]   = make_uint4(pk2(lo[0],lo[1]), pk2(lo[2],lo[3]),
                                            pk2(lo[4],lo[5]), pk2(lo[6],lo[7]));
        *(uint4*)&g_wl[base+8] = make_uint4(pk2(lo[8],lo[9]), pk2(lo[10],lo[11]),
                                            pk2(lo[12],lo[13]), pk2(lo[14],lo[15]));
    }
}

// ---------------------------------------------------------------------------
// K4: out = w @ VP, 2-stage cp.async pipeline. CTA tile 64(t) x 64(j),
// K=256 in 32-chunks. grid (16 j, 16 m, 4 b) = 1024 CTAs, 128 thr
// (4 warps: 2m32 x 2n32).
// ---------------------------------------------------------------------------
#define OT_STG (256*LDT)     // per-stage: A 128 rows (64 hi+64 lo) + B 128 rows

__global__ __launch_bounds__(128) void out_mma(float* __restrict__ out) {
    __shared__ __align__(16) bf16 sm[2*OT_STG];   // 41KB
    const int tid  = threadIdx.x;
    const int nIdx = blockIdx.x;
    const int mIdx = blockIdx.y;
    const int b    = blockIdx.z;
    const int trow0 = b*Tn + mIdx*64;
    const int j0 = nIdx*64;
    const int lane = tid & 31, wid = tid >> 5;
    const int mBase = (wid & 1) * 32, nBase = (wid >> 1) * 32;

    const int aR = (lane & 7) + ((lane >> 3) & 1)*8;
    const int aC = (lane >> 4)*8;
    const int bR = (lane & 7) + (lane >> 4)*8;
    const int bC = ((lane >> 3) & 1)*8;

    float acc[2][4][4];
#pragma unroll
    for (int mb = 0; mb < 2; ++mb)
#pragma unroll
        for (int nb = 0; nb < 4; ++nb)
#pragma unroll
            for (int q = 0; q < 4; ++q) acc[mb][nb][q] = 0.f;

    auto loadStage = [&](int s, int k0) {
        bf16* As = sm + s*OT_STG;
        bf16* Bs = As + 128*LDT;
#pragma unroll
        for (int p = 0; p < 4; ++p) {            // A: 128 rows (hi|lo)
            const int idx = tid + p*128;
            const int r = idx >> 2;
            const int row = r & 63, pl = r >> 6;
            const int col = (idx & 3) * 8;
            const bf16* src = (pl ? g_wl : g_wh) + (trow0 + row)*HKn + k0 + col;
            cpa16(sptr(&As[r*LDT + col]), src);
        }
#pragma unroll
        for (int p = 0; p < 4; ++p) {            // B: 128 rows (hi|lo)
            const int idx = tid + p*128;
            const int r = idx >> 2;
            const int n = r & 63, pl = r >> 6;
            const int col = (idx & 3) * 8;
            const bf16* src = (pl ? g_VPTl : g_VPTh) + (b*Cn + j0 + n)*HKn + k0 + col;
            cpa16(sptr(&Bs[r*LDT + col]), src);
        }
    };

    loadStage(0, 0);
    CP_COMMIT();
    const int nIter = HKn / 32;                  // 8
    for (int it = 0; it < nIter; ++it) {
        bf16* As = sm + (it & 1)*OT_STG;
        bf16* Bs = As + 128*LDT;
        if (it + 1 < nIter) {
            loadStage((it + 1) & 1, (it + 1) * 32);
            CP_COMMIT();
            asm volatile("cp.async.wait_group 1;");
        } else {
            asm volatile("cp.async.wait_group 0;");
        }
        __syncthreads();
#pragma unroll
        for (int kk = 0; kk < 32; kk += 16) {
            uint32_t ah[2][4], al[2][4], bh2[2][4], bl2[2][4];
#pragma unroll
            for (int mb = 0; mb < 2; ++mb) {
                uint32_t ad = sptr(&As[(mBase + mb*16 + aR)*LDT + kk + aC]);
                ldsm4(ah[mb], ad);
                ldsm4(al[mb], ad + 64*LDT*2);
            }
#pragma unroll
            for (int q = 0; q < 2; ++q) {
                uint32_t bd = sptr(&Bs[(nBase + q*16 + bR)*LDT + kk + bC]);
                ldsm4(bh2[q], bd);
                ldsm4(bl2[q], bd + 64*LDT*2);
            }
#pragma unroll
            for (int mb = 0; mb < 2; ++mb)
#pragma unroll
                for (int nb = 0; nb < 4; ++nb) {
                    const uint32_t* bhp = &bh2[nb>>1][(nb&1)*2];
                    const uint32_t* blp = &bl2[nb>>1][(nb&1)*2];
                    mma16816(acc[mb][nb], ah[mb], bhp);
                    mma16816(acc[mb][nb], ah[mb], blp);
                    mma16816(acc[mb][nb], al[mb], bhp);
                }
        }
        __syncthreads();
    }
    const int g = lane >> 2, c2 = (lane & 3) * 2;
#pragma unroll
    for (int mb = 0; mb < 2; ++mb)
#pragma unroll
        for (int nb = 0; nb < 4; ++nb) {
            const int row = trow0 + mBase + mb*16 + g;
            const int col = j0 + nBase + nb*8 + c2;
            *(float2*)&out[row*Cn + col] =
                make_float2(acc[mb][nb][0], acc[mb][nb][1]);
            *(float2*)&out[(row + 8)*Cn + col] =
                make_float2(acc[mb][nb][2], acc[mb][nb][3]);
        }
}

// ---------------------------------------------------------------------------
extern "C" void kernel_launch(void* const* d_in, const int* in_sizes, int n_in,
                              void* d_out, int out_size) {
    const float* x  = (const float*)d_in[0];
    const float* Wa = (const float*)d_in[1];
    const float* Wp = (const float*)d_in[2];
    float* out = (float*)d_out;

    xsplit_kernel<<<dim3(4096),     256>>>(x);
    kv_mma       <<<dim3(16, 8),    256>>>(x, Wa);
    kqvp_kernel  <<<dim3(8, 16, 2), 256>>>(Wa, Wp);
    attn_fused   <<<dim3(4, 32, 4), 128>>>(0);
    out_mma      <<<dim3(16, 16, 4),128>>>(out);
}

// round 14
// speedup vs baseline: 1.0626x; 1.0023x over previous
#include <cuda_runtime.h>
#include <cuda_bf16.h>
#include <cstdint>

// DynamicSparseAttention — sm_103a, round 11.
// top-k indices provably [0..15]; projections re-associated through 16-slot
// attention. mma.sync bf16 3-term hi/lo split (tcgen05 unavailable: harness
// targets sm_103 without 'a'). This round: 64x64 tiles @ 8 warps for attn/out
// (halves L2 traffic, doubles warps), xsplit merged into kv launch.

#define Bn   4
#define Tn   1024
#define Cn   1024
#define Hn   16
#define HDn  64
#define KSn  16
#define HKn  256
#define LDT  40          // smem row stride in bf16 (80B) -> conflict-free ldmatrix

typedef __nv_bfloat16 bf16;

// ---- scratch (static device globals; no allocation allowed) ----
__device__ float g_kvp [8*64*2048];        // kv split-K partials
__device__ bf16  g_xh  [Bn*Tn*Cn];         // x hi plane
__device__ bf16  g_xl  [Bn*Tn*Cn];         // x lo plane
__device__ bf16  g_KQh [Bn*HKn*Cn];        // KQ hi plane (scale 1/8 folded)
__device__ bf16  g_KQl [Bn*HKn*Cn];
__device__ bf16  g_VPTh[Bn*Cn*HKn];        // VP^T [b][j][hk] hi
__device__ bf16  g_VPTl[Bn*Cn*HKn];
__device__ bf16  g_wh  [Bn*Tn*HKn];        // softmax weights hi
__device__ bf16  g_wl  [Bn*Tn*HKn];

// ---- helpers ----
__device__ __forceinline__ uint32_t sptr(const void* p) {
    return (uint32_t)__cvta_generic_to_shared(p);
}
__device__ __forceinline__ void ldsm4(uint32_t* r, uint32_t addr) {
    asm volatile("ldmatrix.sync.aligned.m8n8.x4.shared.b16 {%0,%1,%2,%3}, [%4];"
        : "=r"(r[0]), "=r"(r[1]), "=r"(r[2]), "=r"(r[3]) : "r"(addr));
}
__device__ __forceinline__ void mma16816(float* d, const uint32_t* a, const uint32_t* b) {
    asm volatile("mma.sync.aligned.m16n8k16.row.col.f32.bf16.bf16.f32 "
        "{%0,%1,%2,%3}, {%4,%5,%6,%7}, {%8,%9}, {%0,%1,%2,%3};"
        : "+f"(d[0]), "+f"(d[1]), "+f"(d[2]), "+f"(d[3])
        : "r"(a[0]), "r"(a[1]), "r"(a[2]), "r"(a[3]), "r"(b[0]), "r"(b[1]));
}
__device__ __forceinline__ uint32_t pk2(bf16 a, bf16 b) {
    __nv_bfloat162 t; t.x = a; t.y = b;
    return *reinterpret_cast<uint32_t*>(&t);
}
__device__ __forceinline__ void split2(float v, bf16& h, bf16& l) {
    h = __float2bfloat16_rn(v);
    l = __float2bfloat16_rn(v - __bfloat162float(h));
}
__device__ __forceinline__ void cpa16(uint32_t dst, const void* src) {
    asm volatile("cp.async.cg.shared.global [%0], [%1], 16;" :: "r"(dst), "l"(src));
}
#define CP_COMMIT() asm volatile("cp.async.commit_group;")

// ---------------------------------------------------------------------------
// K1: merged prep. Blocks [0,512): xsplit x fp32 -> bf16 hi/lo planes
// (grid-stride). Blocks [512,640): kv partials via HMMA (split-K x8).
// The two halves are independent and overlap (HBM-bound vs ALU-bound).
// ---------------------------------------------------------------------------
__global__ __launch_bounds__(256) void prep_kernel(const float* __restrict__ x,
                                                   const float* __restrict__ Wa) {
    if (blockIdx.x < 512) {
        const int base = blockIdx.x*256 + threadIdx.x;   // 0..131071
#pragma unroll
        for (int q = 0; q < 8; ++q) {
            const int i = (q*131072 + base) * 4;         // 4M floats total
            float4 v = *(const float4*)&x[i];
            bf16 h0,l0,h1,l1,h2,l2,h3,l3;
            split2(v.x,h0,l0); split2(v.y,h1,l1);
            split2(v.z,h2,l2); split2(v.w,h3,l3);
            *(uint2*)&g_xh[i] = make_uint2(pk2(h0,h1), pk2(h2,h3));
            *(uint2*)&g_xl[i] = make_uint2(pk2(l0,l1), pk2(l2,l3));
        }
        return;
    }
    // ---- kv branch ----
    __shared__ __align__(16) bf16 sm[384*LDT];
    bf16* Ah = sm;
    bf16* Bh = sm + 128*LDT;
    const int bx  = blockIdx.x - 512;      // 0..127
    const int nt  = bx & 15;
    const int ks  = bx >> 4;
    const int tid = threadIdx.x;
    const int lane = tid & 31, wid = tid >> 5;
    const int mBase = (wid & 1) * 32, nBase = (wid >> 1) * 32;

    const int aR = (lane & 7) + ((lane >> 3) & 1)*8;
    const int aC = (lane >> 4)*8;
    const int bR = (lane & 7) + (lane >> 4)*8;
    const int bC = ((lane >> 3) & 1)*8;

    float acc[2][4][4];
#pragma unroll
    for (int mb = 0; mb < 2; ++mb)
#pragma unroll
        for (int nb = 0; nb < 4; ++nb)
#pragma unroll
            for (int q = 0; q < 4; ++q) acc[mb][nb][q] = 0.f;

    for (int k0 = ks*128; k0 < ks*128 + 128; k0 += 32) {
#pragma unroll
        for (int p = 0; p < 2; ++p) {
            const int idx = tid + p*256;
            const int row = idx >> 3, kq = (idx & 7) * 4;
            const int b = row >> 4, s = row & 15;
            float4 v = *(const float4*)&x[(b*Tn + s)*Cn + k0 + kq];
            bf16 hx,lx,hy,ly,hz,lz,hw,lw;
            split2(v.x,hx,lx); split2(v.y,hy,ly);
            split2(v.z,hz,lz); split2(v.w,hw,lw);
            *(uint2*)&Ah[row*LDT + kq]          = make_uint2(pk2(hx,hy), pk2(hz,hw));
            *(uint2*)&Ah[64*LDT + row*LDT + kq] = make_uint2(pk2(lx,ly), pk2(lz,lw));
        }
#pragma unroll
        for (int p = 0; p < 4; ++p) {
            const int idx = tid + p*256;
            const int row = idx >> 3, kq = (idx & 7) * 4;
            float4 v = *(const float4*)&Wa[(Cn + nt*128 + row)*Cn + k0 + kq];
            bf16 hx,lx,hy,ly,hz,lz,hw,lw;
            split2(v.x,hx,lx); split2(v.y,hy,ly);
            split2(v.z,hz,lz); split2(v.w,hw,lw);
            *(uint2*)&Bh[row*LDT + kq]           = make_uint2(pk2(hx,hy), pk2(hz,hw));
            *(uint2*)&Bh[128*LDT + row*LDT + kq] = make_uint2(pk2(lx,ly), pk2(lz,lw));
        }
        __syncthreads();
#pragma unroll
        for (int kk = 0; kk < 32; kk += 16) {
            uint32_t ah[2][4], al[2][4], bh2[2][4], bl2[2][4];
#pragma unroll
            for (int mb = 0; mb < 2; ++mb) {
                uint32_t ad = sptr(&Ah[(mBase + mb*16 + aR)*LDT + kk + aC]);
                ldsm4(ah[mb], ad);
                ldsm4(al[mb], ad + 64*LDT*2);
            }
#pragma unroll
            for (int q = 0; q < 2; ++q) {
                uint32_t bd = sptr(&Bh[(nBase + q*16 + bR)*LDT + kk + bC]);
                ldsm4(bh2[q], bd);
                ldsm4(bl2[q], bd + 128*LDT*2);
            }
#pragma unroll
            for (int mb = 0; mb < 2; ++mb)
#pragma unroll
                for (int nb = 0; nb < 4; ++nb) {
                    const uint32_t* bhp = &bh2[nb>>1][(nb&1)*2];
                    const uint32_t* blp = &bl2[nb>>1][(nb&1)*2];
                    mma16816(acc[mb][nb], ah[mb], bhp);
                    mma16816(acc[mb][nb], ah[mb], blp);
                    mma16816(acc[mb][nb], al[mb], bhp);
                }
        }
        __syncthreads();
    }
    const int g = lane >> 2, c2 = (lane & 3) * 2;
#pragma unroll
    for (int mb = 0; mb < 2; ++mb)
#pragma unroll
        for (int nb = 0; nb < 4; ++nb) {
            const int row = mBase + mb*16 + g;
            const int col = nt*128 + nBase + nb*8 + c2;
            *(float2*)&g_kvp[(ks*64 + row)*2048 + col] =
                make_float2(acc[mb][nb][0], acc[mb][nb][1]);
            *(float2*)&g_kvp[(ks*64 + row + 8)*2048 + col] =
                make_float2(acc[mb][nb][2], acc[mb][nb][3]);
        }
}

// ---------------------------------------------------------------------------
// K2: merged KQ / VP^T, reducing 8 kv partials inline (unchanged, proven).
// ---------------------------------------------------------------------------
__global__ __launch_bounds__(256) void kqvp_kernel(const float* __restrict__ Wa,
                                                   const float* __restrict__ Wp) {
    __shared__ float smem[12288];
    float (*Ws)[128] = (float(*)[128])smem;
    float (*ts)[64]  = (float(*)[64])(smem + 8192);
    const int ct  = blockIdx.x;
    const int h   = blockIdx.y;
    const int z   = blockIdx.z;
    const int tid = threadIdx.x;
    const int vcol = (z == 0) ? h*HDn : 1024 + h*HDn;

    if (z == 0) {
#pragma unroll
        for (int p = 0; p < 8; ++p) {
            const int idx = tid + p*256;
            const int d   = idx >> 5;
            const int f4  = (idx & 31) << 2;
            float4 v = *(const float4*)&Wa[(h*HDn + d)*Cn + ct*128 + f4];
            *(float4*)&Ws[d][f4] = v;
        }
    } else {
#pragma unroll
        for (int p = 0; p < 8; ++p) {
            const int idx = tid + p*256;
            const int j   = idx >> 4;
            const int f4  = (idx & 15) << 2;
            float4 v = *(const float4*)&Wp[(ct*128 + j)*Cn + h*HDn + f4];
            Ws[f4+0][j] = v.x; Ws[f4+1][j] = v.y;
            Ws[f4+2][j] = v.z; Ws[f4+3][j] = v.w;
        }
    }
#pragma unroll
    for (int p = 0; p < 4; ++p) {
        const int idx = tid + p*256;
        const int r   = idx >> 4;
        const int f4  = (idx & 15) << 2;
        float4 s = make_float4(0.f, 0.f, 0.f, 0.f);
#pragma unroll
        for (int ksp = 0; ksp < 8; ++ksp) {
            float4 v = *(const float4*)&g_kvp[(ksp*64 + r)*2048 + vcol + f4];
            s.x += v.x; s.y += v.y; s.z += v.z; s.w += v.w;
        }
        ts[f4+0][r] = s.x; ts[f4+1][r] = s.y;
        ts[f4+2][r] = s.z; ts[f4+3][r] = s.w;
    }
    __syncthreads();

    const int r0 = (tid >> 4) << 2;
    const int c0 = (tid & 15) << 3;
    float acc[4][8];
#pragma unroll
    for (int i = 0; i < 4; ++i)
#pragma unroll
        for (int j = 0; j < 8; ++j) acc[i][j] = 0.f;

#pragma unroll 8
    for (int d = 0; d < 64; ++d) {
        float4 a  = *(const float4*)&ts[d][r0];
        float4 b0 = *(const float4*)&Ws[d][c0];
        float4 b1 = *(const float4*)&Ws[d][c0+4];
        const float av[4] = {a.x, a.y, a.z, a.w};
        const float bv[8] = {b0.x,b0.y,b0.z,b0.w,b1.x,b1.y,b1.z,b1.w};
#pragma unroll
        for (int i = 0; i < 4; ++i)
#pragma unroll
            for (int j = 0; j < 8; ++j) acc[i][j] += av[i]*bv[j];
    }

    if (z == 0) {
#pragma unroll
        for (int i = 0; i < 4; ++i) {
            const int r = r0 + i, b = r >> 4, s = r & 15;
            const int base = (b*HKn + h*KSn + s)*Cn + ct*128 + c0;
            bf16 hi[8], lo[8];
#pragma unroll
            for (int j = 0; j < 8; ++j) split2(acc[i][j] * 0.125f, hi[j], lo[j]);
            *(uint4*)&g_KQh[base] = make_uint4(pk2(hi[0],hi[1]), pk2(hi[2],hi[3]),
                                               pk2(hi[4],hi[5]), pk2(hi[6],hi[7]));
            *(uint4*)&g_KQl[base] = make_uint4(pk2(lo[0],lo[1]), pk2(lo[2],lo[3]),
                                               pk2(lo[4],lo[5]), pk2(lo[6],lo[7]));
        }
    } else {
        __syncthreads();
        float* tp = smem;
#pragma unroll
        for (int i = 0; i < 4; ++i)
#pragma unroll
            for (int j = 0; j < 8; ++j)
                tp[(r0+i)*129 + c0 + j] = acc[i][j];
        __syncthreads();
#pragma unroll
        for (int p = 0; p < 2; ++p) {
            const int run = tid + p*256;
            const int bb  = run >> 7;
            const int j   = run & 127;
            bf16 hi[16], lo[16];
#pragma unroll
            for (int s = 0; s < 16; ++s)
                split2(tp[(bb*16 + s)*129 + j], hi[s], lo[s]);
            const int dst = (bb*Cn + ct*128 + j)*HKn + h*KSn;
            *(uint4*)&g_VPTh[dst]   = make_uint4(pk2(hi[0],hi[1]), pk2(hi[2],hi[3]),
                                                 pk2(hi[4],hi[5]), pk2(hi[6],hi[7]));
            *(uint4*)&g_VPTh[dst+8] = make_uint4(pk2(hi[8],hi[9]), pk2(hi[10],hi[11]),
                                                 pk2(hi[12],hi[13]), pk2(hi[14],hi[15]));
            *(uint4*)&g_VPTl[dst]   = make_uint4(pk2(lo[0],lo[1]), pk2(lo[2],lo[3]),
                                                 pk2(lo[4],lo[5]), pk2(lo[6],lo[7]));
            *(uint4*)&g_VPTl[dst+8] = make_uint4(pk2(lo[8],lo[9]), pk2(lo[10],lo[11]),
                                                 pk2(lo[12],lo[13]), pk2(lo[14],lo[15]));
        }
    }
}

// ---------------------------------------------------------------------------
// K3: logits = x @ KQ^T + fused softmax. CTA tile 64(t) x 64(hk = 4 whole
// heads), K=1024, chunk 32, 2-stage cp.async. grid (4 n, 16 m, 4 b) = 256
// CTAs, 256 thr (8 warps: 4m16 x 2n32). Stage = 256 rows x 80B, 40KB total.
// ---------------------------------------------------------------------------
#define AT_STG (256*LDT)

__global__ __launch_bounds__(256) void attn_fused() {
    __shared__ __align__(16) bf16 sm[2*AT_STG];   // 40KB
    const int tid  = threadIdx.x;
    const int nIdx = blockIdx.x;
    const int mIdx = blockIdx.y;
    const int b    = blockIdx.z;
    const int trow0 = b*Tn + mIdx*64;
    const int n0 = nIdx*64;
    const int lane = tid & 31, wid = tid >> 5;
    const int mW = (wid & 3) * 16, nW = (wid >> 2) * 32;

    const int aR = (lane & 7) + ((lane >> 3) & 1)*8;
    const int aC = (lane >> 4)*8;
    const int bR = (lane & 7) + (lane >> 4)*8;
    const int bC = ((lane >> 3) & 1)*8;

    float acc[4][4];
#pragma unroll
    for (int nb = 0; nb < 4; ++nb)
#pragma unroll
        for (int q = 0; q < 4; ++q) acc[nb][q] = 0.f;

    auto loadStage = [&](int s, int k0) {
        bf16* As = sm + s*AT_STG;
        bf16* Bs = As + 128*LDT;
#pragma unroll
        for (int p = 0; p < 2; ++p) {            // A: 128 rows (64 hi + 64 lo)
            const int idx = tid + p*256;
            const int r = idx >> 2;              // 0..127
            const int c = (idx & 3) * 8;
            const bf16* src = ((r & 64) ? g_xl : g_xh)
                            + (trow0 + (r & 63))*Cn + k0 + c;
            cpa16(sptr(&As[r*LDT + c]), src);
        }
#pragma unroll
        for (int p = 0; p < 2; ++p) {            // B: 128 rows (64 hi + 64 lo)
            const int idx = tid + p*256;
            const int r = idx >> 2;
            const int c = (idx & 3) * 8;
            const bf16* src = ((r & 64) ? g_KQl : g_KQh)
                            + (b*HKn + n0 + (r & 63))*Cn + k0 + c;
            cpa16(sptr(&Bs[r*LDT + c]), src);
        }
    };

    loadStage(0, 0);
    CP_COMMIT();
    for (int it = 0; it < 32; ++it) {
        bf16* As = sm + (it & 1)*AT_STG;
        bf16* Bs = As + 128*LDT;
        if (it + 1 < 32) {
            loadStage((it + 1) & 1, (it + 1) * 32);
            CP_COMMIT();
            asm volatile("cp.async.wait_group 1;" ::: "memory");
        } else {
            asm volatile("cp.async.wait_group 0;" ::: "memory");
        }
        __syncthreads();
#pragma unroll
        for (int kk = 0; kk < 32; kk += 16) {
            uint32_t ah[4], al[4], bh2[2][4], bl2[2][4];
            uint32_t ad = sptr(&As[(mW + aR)*LDT + kk + aC]);
            ldsm4(ah, ad);
            ldsm4(al, ad + 64*LDT*2);
#pragma unroll
            for (int q = 0; q < 2; ++q) {
                uint32_t bd = sptr(&Bs[(nW + q*16 + bR)*LDT + kk + bC]);
                ldsm4(bh2[q], bd);
                ldsm4(bl2[q], bd + 64*LDT*2);
            }
#pragma unroll
            for (int nb = 0; nb < 4; ++nb) {
                const uint32_t* bhp = &bh2[nb>>1][(nb&1)*2];
                const uint32_t* blp = &bl2[nb>>1][(nb&1)*2];
                mma16816(acc[nb], ah, bhp);
                mma16816(acc[nb], ah, blp);
                mma16816(acc[nb], al, bhp);
            }
        }
        __syncthreads();
    }

    // stage logits (64 x 64, stride 68 floats = 17.4KB, fits in sm)
    float* lg = (float*)sm;
    const int g = lane >> 2, c2 = (lane & 3) * 2;
#pragma unroll
    for (int nb = 0; nb < 4; ++nb) {
        const int row = mW + g;
        const int col = nW + nb*8 + c2;
        *(float2*)&lg[row*68 + col]     = make_float2(acc[nb][0], acc[nb][1]);
        *(float2*)&lg[(row+8)*68 + col] = make_float2(acc[nb][2], acc[nb][3]);
    }
    __syncthreads();

    // masked softmax: 64 rows x 4 heads = 256 groups, 1 per thread
    {
        const int tl = tid >> 2;                 // 0..63
        const int hl = tid & 3;
        const int tb = mIdx*64 + tl;
        const int cnt = (tb + 1 < KSn) ? tb + 1 : KSn;
        const float* rowp = &lg[tl*68 + hl*16];
        float m = -3.0e38f;
#pragma unroll
        for (int s = 0; s < KSn; ++s) if (s < cnt) m = fmaxf(m, rowp[s]);
        float e[KSn]; float sum = 0.f;
#pragma unroll
        for (int s = 0; s < KSn; ++s) {
            float v = (s < cnt) ? expf(rowp[s] - m) : 0.f;
            e[s] = v; sum += v;
        }
        const float inv = 1.f / sum;
        bf16 hi[16], lo[16];
#pragma unroll
        for (int s = 0; s < KSn; ++s) split2(e[s]*inv, hi[s], lo[s]);
        const int base = (b*Tn + tb)*HKn + n0 + hl*16;
        *(uint4*)&g_wh[base]   = make_uint4(pk2(hi[0],hi[1]), pk2(hi[2],hi[3]),
                                            pk2(hi[4],hi[5]), pk2(hi[6],hi[7]));
        *(uint4*)&g_wh[base+8] = make_uint4(pk2(hi[8],hi[9]), pk2(hi[10],hi[11]),
                                            pk2(hi[12],hi[13]), pk2(hi[14],hi[15]));
        *(uint4*)&g_wl[base]   = make_uint4(pk2(lo[0],lo[1]), pk2(lo[2],lo[3]),
                                            pk2(lo[4],lo[5]), pk2(lo[6],lo[7]));
        *(uint4*)&g_wl[base+8] = make_uint4(pk2(lo[8],lo[9]), pk2(lo[10],lo[11]),
                                            pk2(lo[12],lo[13]), pk2(lo[14],lo[15]));
    }
}

// ---------------------------------------------------------------------------
// K4: out = w @ VP. CTA tile 64(t) x 64(j), K=256, chunk 32, 2-stage
// cp.async. grid (16 j, 16 m, 4 b) = 1024 CTAs, 256 thr (8 warps: 4m x 2n).
// ---------------------------------------------------------------------------
#define OT_STG (256*LDT)

__global__ __launch_bounds__(256) void out_mma(float* __restrict__ out) {
    __shared__ __align__(16) bf16 sm[2*OT_STG];   // 40KB
    const int tid  = threadIdx.x;
    const int nIdx = blockIdx.x;
    const int mIdx = blockIdx.y;
    const int b    = blockIdx.z;
    const int trow0 = b*Tn + mIdx*64;
    const int j0 = nIdx*64;
    const int lane = tid & 31, wid = tid >> 5;
    const int mW = (wid & 3) * 16, nW = (wid >> 2) * 32;

    const int aR = (lane & 7) + ((lane >> 3) & 1)*8;
    const int aC = (lane >> 4)*8;
    const int bR = (lane & 7) + (lane >> 4)*8;
    const int bC = ((lane >> 3) & 1)*8;

    float acc[4][4];
#pragma unroll
    for (int nb = 0; nb < 4; ++nb)
#pragma unroll
        for (int q = 0; q < 4; ++q) acc[nb][q] = 0.f;

    auto loadStage = [&](int s, int k0) {
        bf16* As = sm + s*OT_STG;
        bf16* Bs = As + 128*LDT;
#pragma unroll
        for (int p = 0; p < 2; ++p) {            // A: w planes
            const int idx = tid + p*256;
            const int r = idx >> 2;
            const int c = (idx & 3) * 8;
            const bf16* src = ((r & 64) ? g_wl : g_wh)
                            + (trow0 + (r & 63))*HKn + k0 + c;
            cpa16(sptr(&As[r*LDT + c]), src);
        }
#pragma unroll
        for (int p = 0; p < 2; ++p) {            // B: VPT planes
            const int idx = tid + p*256;
            const int r = idx >> 2;
            const int c = (idx & 3) * 8;
            const bf16* src = ((r & 64) ? g_VPTl : g_VPTh)
                            + (b*Cn + j0 + (r & 63))*HKn + k0 + c;
            cpa16(sptr(&Bs[r*LDT + c]), src);
        }
    };

    loadStage(0, 0);
    CP_COMMIT();
    for (int it = 0; it < 8; ++it) {
        bf16* As = sm + (it & 1)*OT_STG;
        bf16* Bs = As + 128*LDT;
        if (it + 1 < 8) {
            loadStage((it + 1) & 1, (it + 1) * 32);
            CP_COMMIT();
            asm volatile("cp.async.wait_group 1;" ::: "memory");
        } else {
            asm volatile("cp.async.wait_group 0;" ::: "memory");
        }
        __syncthreads();
#pragma unroll
        for (int kk = 0; kk < 32; kk += 16) {
            uint32_t ah[4], al[4], bh2[2][4], bl2[2][4];
            uint32_t ad = sptr(&As[(mW + aR)*LDT + kk + aC]);
            ldsm4(ah, ad);
            ldsm4(al, ad + 64*LDT*2);
#pragma unroll
            for (int q = 0; q < 2; ++q) {
                uint32_t bd = sptr(&Bs[(nW + q*16 + bR)*LDT + kk + bC]);
                ldsm4(bh2[q], bd);
                ldsm4(bl2[q], bd + 64*LDT*2);
            }
#pragma unroll
            for (int nb = 0; nb < 4; ++nb) {
                const uint32_t* bhp = &bh2[nb>>1][(nb&1)*2];
                const uint32_t* blp = &bl2[nb>>1][(nb&1)*2];
                mma16816(acc[nb], ah, bhp);
                mma16816(acc[nb], ah, blp);
                mma16816(acc[nb], al, bhp);
            }
        }
        __syncthreads();
    }
    const int g = lane >> 2, c2 = (lane & 3) * 2;
#pragma unroll
    for (int nb = 0; nb < 4; ++nb) {
        const int row = trow0 + mW + g;
        const int col = j0 + nW + nb*8 + c2;
        *(float2*)&out[row*Cn + col]     = make_float2(acc[nb][0], acc[nb][1]);
        *(float2*)&out[(row + 8)*Cn + col] = make_float2(acc[nb][2], acc[nb][3]);
    }
}

// ---------------------------------------------------------------------------
extern "C" void kernel_launch(void* const* d_in, const int* in_sizes, int n_in,
                              void* d_out, int out_size) {
    const float* x  = (const float*)d_in[0];
    const float* Wa = (const float*)d_in[1];
    const float* Wp = (const float*)d_in[2];
    float* out = (float*)d_out;

    prep_kernel <<<dim3(640),       256>>>(x, Wa);
    kqvp_kernel <<<dim3(8, 16, 2),  256>>>(Wa, Wp);
    attn_fused  <<<dim3(4, 16, 4),  256>>>();
    out_mma     <<<dim3(16, 16, 4), 256>>>(out);
}

// round 15
// speedup vs baseline: 1.1545x; 1.0864x over previous
#include <cuda_runtime.h>
#include <cuda_bf16.h>
#include <cstdint>

// DynamicSparseAttention — sm_103a, round 15.
// top-k indices provably [0..15]; projections re-associated through 16-slot
// attention. mma.sync bf16 3-term hi/lo split (tcgen05 rejected: harness
// targets sm_103 non-'a'). This round: k-chunk 32->64 in attn/out so the
// compute phase (~384cyc) exceeds L2 latency (~262cyc) and the 2-stage
// cp.async pipeline actually covers it; dynamic smem (72KB, 2 CTA/SM).

#define Bn   4
#define Tn   1024
#define Cn   1024
#define Hn   16
#define HDn  64
#define KSn  16
#define HKn  256
#define LDT  40          // prep kernel row stride (chunk 32)
#define LD2  72          // attn/out row stride in bf16 (144B) for chunk 64

typedef __nv_bfloat16 bf16;

// ---- scratch (static device globals; no allocation allowed) ----
__device__ float g_kvp [8*64*2048];        // kv split-K partials
__device__ bf16  g_xh  [Bn*Tn*Cn];         // x hi plane
__device__ bf16  g_xl  [Bn*Tn*Cn];         // x lo plane
__device__ bf16  g_KQh [Bn*HKn*Cn];        // KQ hi plane (scale 1/8 folded)
__device__ bf16  g_KQl [Bn*HKn*Cn];
__device__ bf16  g_VPTh[Bn*Cn*HKn];        // VP^T [b][j][hk] hi
__device__ bf16  g_VPTl[Bn*Cn*HKn];
__device__ bf16  g_wh  [Bn*Tn*HKn];        // softmax weights hi
__device__ bf16  g_wl  [Bn*Tn*HKn];

// ---- helpers ----
__device__ __forceinline__ uint32_t sptr(const void* p) {
    return (uint32_t)__cvta_generic_to_shared(p);
}
__device__ __forceinline__ void ldsm4(uint32_t* r, uint32_t addr) {
    asm volatile("ldmatrix.sync.aligned.m8n8.x4.shared.b16 {%0,%1,%2,%3}, [%4];"
        : "=r"(r[0]), "=r"(r[1]), "=r"(r[2]), "=r"(r[3]) : "r"(addr));
}
__device__ __forceinline__ void mma16816(float* d, const uint32_t* a, const uint32_t* b) {
    asm volatile("mma.sync.aligned.m16n8k16.row.col.f32.bf16.bf16.f32 "
        "{%0,%1,%2,%3}, {%4,%5,%6,%7}, {%8,%9}, {%0,%1,%2,%3};"
        : "+f"(d[0]), "+f"(d[1]), "+f"(d[2]), "+f"(d[3])
        : "r"(a[0]), "r"(a[1]), "r"(a[2]), "r"(a[3]), "r"(b[0]), "r"(b[1]));
}
__device__ __forceinline__ uint32_t pk2(bf16 a, bf16 b) {
    __nv_bfloat162 t; t.x = a; t.y = b;
    return *reinterpret_cast<uint32_t*>(&t);
}
__device__ __forceinline__ void split2(float v, bf16& h, bf16& l) {
    h = __float2bfloat16_rn(v);
    l = __float2bfloat16_rn(v - __bfloat162float(h));
}
__device__ __forceinline__ void cpa16(uint32_t dst, const void* src) {
    asm volatile("cp.async.cg.shared.global [%0], [%1], 16;" :: "r"(dst), "l"(src));
}
#define CP_COMMIT() asm volatile("cp.async.commit_group;")

// ---------------------------------------------------------------------------
// K1: merged prep. Blocks [0,512): xsplit. Blocks [512,640): kv HMMA.
// ---------------------------------------------------------------------------
__global__ __launch_bounds__(256) void prep_kernel(const float* __restrict__ x,
                                                   const float* __restrict__ Wa) {
    if (blockIdx.x < 512) {
        const int base = blockIdx.x*256 + threadIdx.x;
#pragma unroll
        for (int q = 0; q < 8; ++q) {
            const int i = (q*131072 + base) * 4;
            float4 v = *(const float4*)&x[i];
            bf16 h0,l0,h1,l1,h2,l2,h3,l3;
            split2(v.x,h0,l0); split2(v.y,h1,l1);
            split2(v.z,h2,l2); split2(v.w,h3,l3);
            *(uint2*)&g_xh[i] = make_uint2(pk2(h0,h1), pk2(h2,h3));
            *(uint2*)&g_xl[i] = make_uint2(pk2(l0,l1), pk2(l2,l3));
        }
        return;
    }
    __shared__ __align__(16) bf16 sm[384*LDT];
    bf16* Ah = sm;
    bf16* Bh = sm + 128*LDT;
    const int bx  = blockIdx.x - 512;
    const int nt  = bx & 15;
    const int ks  = bx >> 4;
    const int tid = threadIdx.x;
    const int lane = tid & 31, wid = tid >> 5;
    const int mBase = (wid & 1) * 32, nBase = (wid >> 1) * 32;

    const int aR = (lane & 7) + ((lane >> 3) & 1)*8;
    const int aC = (lane >> 4)*8;
    const int bR = (lane & 7) + (lane >> 4)*8;
    const int bC = ((lane >> 3) & 1)*8;

    float acc[2][4][4];
#pragma unroll
    for (int mb = 0; mb < 2; ++mb)
#pragma unroll
        for (int nb = 0; nb < 4; ++nb)
#pragma unroll
            for (int q = 0; q < 4; ++q) acc[mb][nb][q] = 0.f;

    for (int k0 = ks*128; k0 < ks*128 + 128; k0 += 32) {
#pragma unroll
        for (int p = 0; p < 2; ++p) {
            const int idx = tid + p*256;
            const int row = idx >> 3, kq = (idx & 7) * 4;
            const int b = row >> 4, s = row & 15;
            float4 v = *(const float4*)&x[(b*Tn + s)*Cn + k0 + kq];
            bf16 hx,lx,hy,ly,hz,lz,hw,lw;
            split2(v.x,hx,lx); split2(v.y,hy,ly);
            split2(v.z,hz,lz); split2(v.w,hw,lw);
            *(uint2*)&Ah[row*LDT + kq]          = make_uint2(pk2(hx,hy), pk2(hz,hw));
            *(uint2*)&Ah[64*LDT + row*LDT + kq] = make_uint2(pk2(lx,ly), pk2(lz,lw));
        }
#pragma unroll
        for (int p = 0; p < 4; ++p) {
            const int idx = tid + p*256;
            const int row = idx >> 3, kq = (idx & 7) * 4;
            float4 v = *(const float4*)&Wa[(Cn + nt*128 + row)*Cn + k0 + kq];
            bf16 hx,lx,hy,ly,hz,lz,hw,lw;
            split2(v.x,hx,lx); split2(v.y,hy,ly);
            split2(v.z,hz,lz); split2(v.w,hw,lw);
            *(uint2*)&Bh[row*LDT + kq]           = make_uint2(pk2(hx,hy), pk2(hz,hw));
            *(uint2*)&Bh[128*LDT + row*LDT + kq] = make_uint2(pk2(lx,ly), pk2(lz,lw));
        }
        __syncthreads();
#pragma unroll
        for (int kk = 0; kk < 32; kk += 16) {
            uint32_t ah[2][4], al[2][4], bh2[2][4], bl2[2][4];
#pragma unroll
            for (int mb = 0; mb < 2; ++mb) {
                uint32_t ad = sptr(&Ah[(mBase + mb*16 + aR)*LDT + kk + aC]);
                ldsm4(ah[mb], ad);
                ldsm4(al[mb], ad + 64*LDT*2);
            }
#pragma unroll
            for (int q = 0; q < 2; ++q) {
                uint32_t bd = sptr(&Bh[(nBase + q*16 + bR)*LDT + kk + bC]);
                ldsm4(bh2[q], bd);
                ldsm4(bl2[q], bd + 128*LDT*2);
            }
#pragma unroll
            for (int mb = 0; mb < 2; ++mb)
#pragma unroll
                for (int nb = 0; nb < 4; ++nb) {
                    const uint32_t* bhp = &bh2[nb>>1][(nb&1)*2];
                    const uint32_t* blp = &bl2[nb>>1][(nb&1)*2];
                    mma16816(acc[mb][nb], ah[mb], bhp);
                    mma16816(acc[mb][nb], ah[mb], blp);
                    mma16816(acc[mb][nb], al[mb], bhp);
                }
        }
        __syncthreads();
    }
    const int g = lane >> 2, c2 = (lane & 3) * 2;
#pragma unroll
    for (int mb = 0; mb < 2; ++mb)
#pragma unroll
        for (int nb = 0; nb < 4; ++nb) {
            const int row = mBase + mb*16 + g;
            const int col = nt*128 + nBase + nb*8 + c2;
            *(float2*)&g_kvp[(ks*64 + row)*2048 + col] =
                make_float2(acc[mb][nb][0], acc[mb][nb][1]);
            *(float2*)&g_kvp[(ks*64 + row + 8)*2048 + col] =
                make_float2(acc[mb][nb][2], acc[mb][nb][3]);
        }
}

// ---------------------------------------------------------------------------
// K2: merged KQ / VP^T, reducing 8 kv partials inline (unchanged, proven).
// ---------------------------------------------------------------------------
__global__ __launch_bounds__(256) void kqvp_kernel(const float* __restrict__ Wa,
                                                   const float* __restrict__ Wp) {
    __shared__ float smem[12288];
    float (*Ws)[128] = (float(*)[128])smem;
    float (*ts)[64]  = (float(*)[64])(smem + 8192);
    const int ct  = blockIdx.x;
    const int h   = blockIdx.y;
    const int z   = blockIdx.z;
    const int tid = threadIdx.x;
    const int vcol = (z == 0) ? h*HDn : 1024 + h*HDn;

    if (z == 0) {
#pragma unroll
        for (int p = 0; p < 8; ++p) {
            const int idx = tid + p*256;
            const int d   = idx >> 5;
            const int f4  = (idx & 31) << 2;
            float4 v = *(const float4*)&Wa[(h*HDn + d)*Cn + ct*128 + f4];
            *(float4*)&Ws[d][f4] = v;
        }
    } else {
#pragma unroll
        for (int p = 0; p < 8; ++p) {
            const int idx = tid + p*256;
            const int j   = idx >> 4;
            const int f4  = (idx & 15) << 2;
            float4 v = *(const float4*)&Wp[(ct*128 + j)*Cn + h*HDn + f4];
            Ws[f4+0][j] = v.x; Ws[f4+1][j] = v.y;
            Ws[f4+2][j] = v.z; Ws[f4+3][j] = v.w;
        }
    }
#pragma unroll
    for (int p = 0; p < 4; ++p) {
        const int idx = tid + p*256;
        const int r   = idx >> 4;
        const int f4  = (idx & 15) << 2;
        float4 s = make_float4(0.f, 0.f, 0.f, 0.f);
#pragma unroll
        for (int ksp = 0; ksp < 8; ++ksp) {
            float4 v = *(const float4*)&g_kvp[(ksp*64 + r)*2048 + vcol + f4];
            s.x += v.x; s.y += v.y; s.z += v.z; s.w += v.w;
        }
        ts[f4+0][r] = s.x; ts[f4+1][r] = s.y;
        ts[f4+2][r] = s.z; ts[f4+3][r] = s.w;
    }
    __syncthreads();

    const int r0 = (tid >> 4) << 2;
    const int c0 = (tid & 15) << 3;
    float acc[4][8];
#pragma unroll
    for (int i = 0; i < 4; ++i)
#pragma unroll
        for (int j = 0; j < 8; ++j) acc[i][j] = 0.f;

#pragma unroll 8
    for (int d = 0; d < 64; ++d) {
        float4 a  = *(const float4*)&ts[d][r0];
        float4 b0 = *(const float4*)&Ws[d][c0];
        float4 b1 = *(const float4*)&Ws[d][c0+4];
        const float av[4] = {a.x, a.y, a.z, a.w};
        const float bv[8] = {b0.x,b0.y,b0.z,b0.w,b1.x,b1.y,b1.z,b1.w};
#pragma unroll
        for (int i = 0; i < 4; ++i)
#pragma unroll
            for (int j = 0; j < 8; ++j) acc[i][j] += av[i]*bv[j];
    }

    if (z == 0) {
#pragma unroll
        for (int i = 0; i < 4; ++i) {
            const int r = r0 + i, b = r >> 4, s = r & 15;
            const int base = (b*HKn + h*KSn + s)*Cn + ct*128 + c0;
            bf16 hi[8], lo[8];
#pragma unroll
            for (int j = 0; j < 8; ++j) split2(acc[i][j] * 0.125f, hi[j], lo[j]);
            *(uint4*)&g_KQh[base] = make_uint4(pk2(hi[0],hi[1]), pk2(hi[2],hi[3]),
                                               pk2(hi[4],hi[5]), pk2(hi[6],hi[7]));
            *(uint4*)&g_KQl[base] = make_uint4(pk2(lo[0],lo[1]), pk2(lo[2],lo[3]),
                                               pk2(lo[4],lo[5]), pk2(lo[6],lo[7]));
        }
    } else {
        __syncthreads();
        float* tp = smem;
#pragma unroll
        for (int i = 0; i < 4; ++i)
#pragma unroll
            for (int j = 0; j < 8; ++j)
                tp[(r0+i)*129 + c0 + j] = acc[i][j];
        __syncthreads();
#pragma unroll
        for (int p = 0; p < 2; ++p) {
            const int run = tid + p*256;
            const int bb  = run >> 7;
            const int j   = run & 127;
            bf16 hi[16], lo[16];
#pragma unroll
            for (int s = 0; s < 16; ++s)
                split2(tp[(bb*16 + s)*129 + j], hi[s], lo[s]);
            const int dst = (bb*Cn + ct*128 + j)*HKn + h*KSn;
            *(uint4*)&g_VPTh[dst]   = make_uint4(pk2(hi[0],hi[1]), pk2(hi[2],hi[3]),
                                                 pk2(hi[4],hi[5]), pk2(hi[6],hi[7]));
            *(uint4*)&g_VPTh[dst+8] = make_uint4(pk2(hi[8],hi[9]), pk2(hi[10],hi[11]),
                                                 pk2(hi[12],hi[13]), pk2(hi[14],hi[15]));
            *(uint4*)&g_VPTl[dst]   = make_uint4(pk2(lo[0],lo[1]), pk2(lo[2],lo[3]),
                                                 pk2(lo[4],lo[5]), pk2(lo[6],lo[7]));
            *(uint4*)&g_VPTl[dst+8] = make_uint4(pk2(lo[8],lo[9]), pk2(lo[10],lo[11]),
                                                 pk2(lo[12],lo[13]), pk2(lo[14],lo[15]));
        }
    }
}

// ---------------------------------------------------------------------------
// K3: logits = x @ KQ^T + fused softmax. CTA 64(t) x 64(hk = 4 heads),
// K=1024 in 16 chunks of 64, 2-stage cp.async, dynamic smem 72KB.
// grid (4 n, 16 m, 4 b) = 256 CTAs, 256 thr (8 warps: 4m16 x 2n32).
// Stage = 256 rows x 144B; compute/chunk ~384cyc > L2 latency.
// ---------------------------------------------------------------------------
#define AT_STG (256*LD2)      // bf16 elements per stage

__global__ __launch_bounds__(256) void attn_fused() {
    extern __shared__ __align__(16) bf16 sm[];    // 2*AT_STG = 72KB
    const int tid  = threadIdx.x;
    const int nIdx = blockIdx.x;
    const int mIdx = blockIdx.y;
    const int b    = blockIdx.z;
    const int trow0 = b*Tn + mIdx*64;
    const int n0 = nIdx*64;
    const int lane = tid & 31, wid = tid >> 5;
    const int mW = (wid & 3) * 16, nW = (wid >> 2) * 32;

    const int aR = (lane & 7) + ((lane >> 3) & 1)*8;
    const int aC = (lane >> 4)*8;
    const int bR = (lane & 7) + (lane >> 4)*8;
    const int bC = ((lane >> 3) & 1)*8;

    float acc[4][4];
#pragma unroll
    for (int nb = 0; nb < 4; ++nb)
#pragma unroll
        for (int q = 0; q < 4; ++q) acc[nb][q] = 0.f;

    auto loadStage = [&](int s, int k0) {
        bf16* As = sm + s*AT_STG;
        bf16* Bs = As + 128*LD2;
#pragma unroll
        for (int p = 0; p < 4; ++p) {            // A: 128 rows (64 hi + 64 lo)
            const int idx = tid + p*256;
            const int r = idx >> 3;              // 0..127
            const int c = (idx & 7) * 8;         // 0..56
            const bf16* src = ((r & 64) ? g_xl : g_xh)
                            + (trow0 + (r & 63))*Cn + k0 + c;
            cpa16(sptr(&As[r*LD2 + c]), src);
        }
#pragma unroll
        for (int p = 0; p < 4; ++p) {            // B: 128 rows (64 hi + 64 lo)
            const int idx = tid + p*256;
            const int r = idx >> 3;
            const int c = (idx & 7) * 8;
            const bf16* src = ((r & 64) ? g_KQl : g_KQh)
                            + (b*HKn + n0 + (r & 63))*Cn + k0 + c;
            cpa16(sptr(&Bs[r*LD2 + c]), src);
        }
    };

    loadStage(0, 0);
    CP_COMMIT();
    for (int it = 0; it < 16; ++it) {
        bf16* As = sm + (it & 1)*AT_STG;
        bf16* Bs = As + 128*LD2;
        if (it + 1 < 16) {
            loadStage((it + 1) & 1, (it + 1) * 64);
            CP_COMMIT();
            asm volatile("cp.async.wait_group 1;" ::: "memory");
        } else {
            asm volatile("cp.async.wait_group 0;" ::: "memory");
        }
        __syncthreads();
#pragma unroll
        for (int kk = 0; kk < 64; kk += 16) {
            uint32_t ah[4], al[4], bh2[2][4], bl2[2][4];
            uint32_t ad = sptr(&As[(mW + aR)*LD2 + kk + aC]);
            ldsm4(ah, ad);
            ldsm4(al, ad + 64*LD2*2);
#pragma unroll
            for (int q = 0; q < 2; ++q) {
                uint32_t bd = sptr(&Bs[(nW + q*16 + bR)*LD2 + kk + bC]);
                ldsm4(bh2[q], bd);
                ldsm4(bl2[q], bd + 64*LD2*2);
            }
#pragma unroll
            for (int nb = 0; nb < 4; ++nb) {
                const uint32_t* bhp = &bh2[nb>>1][(nb&1)*2];
                const uint32_t* blp = &bl2[nb>>1][(nb&1)*2];
                mma16816(acc[nb], ah, bhp);
                mma16816(acc[nb], ah, blp);
                mma16816(acc[nb], al, bhp);
            }
        }
        __syncthreads();
    }

    // stage logits (64 x 64, stride 68 floats = 17.4KB, fits in sm)
    float* lg = (float*)sm;
    const int g = lane >> 2, c2 = (lane & 3) * 2;
#pragma unroll
    for (int nb = 0; nb < 4; ++nb) {
        const int row = mW + g;
        const int col = nW + nb*8 + c2;
        *(float2*)&lg[row*68 + col]     = make_float2(acc[nb][0], acc[nb][1]);
        *(float2*)&lg[(row+8)*68 + col] = make_float2(acc[nb][2], acc[nb][3]);
    }
    __syncthreads();

    // masked softmax: 64 rows x 4 heads = 256 groups, 1 per thread
    {
        const int tl = tid >> 2;
        const int hl = tid & 3;
        const int tb = mIdx*64 + tl;
        const int cnt = (tb + 1 < KSn) ? tb + 1 : KSn;
        const float* rowp = &lg[tl*68 + hl*16];
        float m = -3.0e38f;
#pragma unroll
        for (int s = 0; s < KSn; ++s) if (s < cnt) m = fmaxf(m, rowp[s]);
        float e[KSn]; float sum = 0.f;
#pragma unroll
        for (int s = 0; s < KSn; ++s) {
            float v = (s < cnt) ? expf(rowp[s] - m) : 0.f;
            e[s] = v; sum += v;
        }
        const float inv = 1.f / sum;
        bf16 hi[16], lo[16];
#pragma unroll
        for (int s = 0; s < KSn; ++s) split2(e[s]*inv, hi[s], lo[s]);
        const int base = (b*Tn + tb)*HKn + n0 + hl*16;
        *(uint4*)&g_wh[base]   = make_uint4(pk2(hi[0],hi[1]), pk2(hi[2],hi[3]),
                                            pk2(hi[4],hi[5]), pk2(hi[6],hi[7]));
        *(uint4*)&g_wh[base+8] = make_uint4(pk2(hi[8],hi[9]), pk2(hi[10],hi[11]),
                                            pk2(hi[12],hi[13]), pk2(hi[14],hi[15]));
        *(uint4*)&g_wl[base]   = make_uint4(pk2(lo[0],lo[1]), pk2(lo[2],lo[3]),
                                            pk2(lo[4],lo[5]), pk2(lo[6],lo[7]));
        *(uint4*)&g_wl[base+8] = make_uint4(pk2(lo[8],lo[9]), pk2(lo[10],lo[11]),
                                            pk2(lo[12],lo[13]), pk2(lo[14],lo[15]));
    }
}

// ---------------------------------------------------------------------------
// K4: out = w @ VP. CTA 64(t) x 64(j), K=256 in 4 chunks of 64, 2-stage
// cp.async, dynamic smem 72KB. grid (16 j, 16 m, 4 b) = 1024 CTAs, 256 thr.
// ---------------------------------------------------------------------------
#define OT_STG (256*LD2)

__global__ __launch_bounds__(256) void out_mma(float* __restrict__ out) {
    extern __shared__ __align__(16) bf16 sm[];    // 2*OT_STG = 72KB
    const int tid  = threadIdx.x;
    const int nIdx = blockIdx.x;
    const int mIdx = blockIdx.y;
    const int b    = blockIdx.z;
    const int trow0 = b*Tn + mIdx*64;
    const int j0 = nIdx*64;
    const int lane = tid & 31, wid = tid >> 5;
    const int mW = (wid & 3) * 16, nW = (wid >> 2) * 32;

    const int aR = (lane & 7) + ((lane >> 3) & 1)*8;
    const int aC = (lane >> 4)*8;
    const int bR = (lane & 7) + (lane >> 4)*8;
    const int bC = ((lane >> 3) & 1)*8;

    float acc[4][4];
#pragma unroll
    for (int nb = 0; nb < 4; ++nb)
#pragma unroll
        for (int q = 0; q < 4; ++q) acc[nb][q] = 0.f;

    auto loadStage = [&](int s, int k0) {
        bf16* As = sm + s*OT_STG;
        bf16* Bs = As + 128*LD2;
#pragma unroll
        for (int p = 0; p < 4; ++p) {            // A: w planes
            const int idx = tid + p*256;
            const int r = idx >> 3;
            const int c = (idx & 7) * 8;
            const bf16* src = ((r & 64) ? g_wl : g_wh)
                            + (trow0 + (r & 63))*HKn + k0 + c;
            cpa16(sptr(&As[r*LD2 + c]), src);
        }
#pragma unroll
        for (int p = 0; p < 4; ++p) {            // B: VPT planes
            const int idx = tid + p*256;
            const int r = idx >> 3;
            const int c = (idx & 7) * 8;
            const bf16* src = ((r & 64) ? g_VPTl : g_VPTh)
                            + (b*Cn + j0 + (r & 63))*HKn + k0 + c;
            cpa16(sptr(&Bs[r*LD2 + c]), src);
        }
    };

    loadStage(0, 0);
    CP_COMMIT();
    for (int it = 0; it < 4; ++it) {
        bf16* As = sm + (it & 1)*OT_STG;
        bf16* Bs = As + 128*LD2;
        if (it + 1 < 4) {
            loadStage((it + 1) & 1, (it + 1) * 64);
            CP_COMMIT();
            asm volatile("cp.async.wait_group 1;" ::: "memory");
        } else {
            asm volatile("cp.async.wait_group 0;" ::: "memory");
        }
        __syncthreads();
#pragma unroll
        for (int kk = 0; kk < 64; kk += 16) {
            uint32_t ah[4], al[4], bh2[2][4], bl2[2][4];
            uint32_t ad = sptr(&As[(mW + aR)*LD2 + kk + aC]);
            ldsm4(ah, ad);
            ldsm4(al, ad + 64*LD2*2);
#pragma unroll
            for (int q = 0; q < 2; ++q) {
                uint32_t bd = sptr(&Bs[(nW + q*16 + bR)*LD2 + kk + bC]);
                ldsm4(bh2[q], bd);
                ldsm4(bl2[q], bd + 64*LD2*2);
            }
#pragma unroll
            for (int nb = 0; nb < 4; ++nb) {
                const uint32_t* bhp = &bh2[nb>>1][(nb&1)*2];
                const uint32_t* blp = &bl2[nb>>1][(nb&1)*2];
                mma16816(acc[nb], ah, bhp);
                mma16816(acc[nb], ah, blp);
                mma16816(acc[nb], al, bhp);
            }
        }
        __syncthreads();
    }
    const int g = lane >> 2, c2 = (lane & 3) * 2;
#pragma unroll
    for (int nb = 0; nb < 4; ++nb) {
        const int row = trow0 + mW + g;
        const int col = j0 + nW + nb*8 + c2;
        *(float2*)&out[row*Cn + col]       = make_float2(acc[nb][0], acc[nb][1]);
        *(float2*)&out[(row + 8)*Cn + col] = make_float2(acc[nb][2], acc[nb][3]);
    }
}

// ---------------------------------------------------------------------------
extern "C" void kernel_launch(void* const* d_in, const int* in_sizes, int n_in,
                              void* d_out, int out_size) {
    const float* x  = (const float*)d_in[0];
    const float* Wa = (const float*)d_in[1];
    const float* Wp = (const float*)d_in[2];
    float* out = (float*)d_out;

    const int dynA = 2*AT_STG*sizeof(bf16);   // 73728 B
    const int dynO = 2*OT_STG*sizeof(bf16);
    cudaFuncSetAttribute(attn_fused, cudaFuncAttributeMaxDynamicSharedMemorySize, dynA);
    cudaFuncSetAttribute(out_mma,    cudaFuncAttributeMaxDynamicSharedMemorySize, dynO);

    prep_kernel <<<dim3(640),       256>>>(x, Wa);
    kqvp_kernel <<<dim3(8, 16, 2),  256>>>(Wa, Wp);
    attn_fused  <<<dim3(4, 16, 4),  256, dynA>>>();
    out_mma     <<<dim3(16, 16, 4), 256, dynO>>>(out);
}

// round 17
// speedup vs baseline: 1.1654x; 1.0095x over previous
#include <cuda_runtime.h>
#include <cuda_bf16.h>
#include <cstdint>

// DynamicSparseAttention — sm_103a, round 17.
// top-k indices provably [0..15]; projections re-associated through 16-slot
// attention. mma.sync bf16 3-term hi/lo split. 3-stage cp.async pipeline,
// ONE __syncthreads per iteration. R16's attn prefetch-index bug fixed:
// (sIdx+2) wraps to 0, not 2.

#define Bn   4
#define Tn   1024
#define Cn   1024
#define Hn   16
#define HDn  64
#define KSn  16
#define HKn  256
#define LDT  40          // prep kernel row stride (chunk 32)
#define LD2  72          // attn/out row stride in bf16 (144B) for chunk 64

typedef __nv_bfloat16 bf16;

// ---- scratch (static device globals; no allocation allowed) ----
__device__ float g_kvp [8*64*2048];        // kv split-K partials
__device__ bf16  g_xh  [Bn*Tn*Cn];         // x hi plane
__device__ bf16  g_xl  [Bn*Tn*Cn];         // x lo plane
__device__ bf16  g_KQh [Bn*HKn*Cn];        // KQ hi plane (scale 1/8 folded)
__device__ bf16  g_KQl [Bn*HKn*Cn];
__device__ bf16  g_VPTh[Bn*Cn*HKn];        // VP^T [b][j][hk] hi
__device__ bf16  g_VPTl[Bn*Cn*HKn];
__device__ bf16  g_wh  [Bn*Tn*HKn];        // softmax weights hi
__device__ bf16  g_wl  [Bn*Tn*HKn];

// ---- helpers ----
__device__ __forceinline__ uint32_t sptr(const void* p) {
    return (uint32_t)__cvta_generic_to_shared(p);
}
__device__ __forceinline__ void ldsm4(uint32_t* r, uint32_t addr) {
    asm volatile("ldmatrix.sync.aligned.m8n8.x4.shared.b16 {%0,%1,%2,%3}, [%4];"
        : "=r"(r[0]), "=r"(r[1]), "=r"(r[2]), "=r"(r[3]) : "r"(addr));
}
__device__ __forceinline__ void mma16816(float* d, const uint32_t* a, const uint32_t* b) {
    asm volatile("mma.sync.aligned.m16n8k16.row.col.f32.bf16.bf16.f32 "
        "{%0,%1,%2,%3}, {%4,%5,%6,%7}, {%8,%9}, {%0,%1,%2,%3};"
        : "+f"(d[0]), "+f"(d[1]), "+f"(d[2]), "+f"(d[3])
        : "r"(a[0]), "r"(a[1]), "r"(a[2]), "r"(a[3]), "r"(b[0]), "r"(b[1]));
}
__device__ __forceinline__ uint32_t pk2(bf16 a, bf16 b) {
    __nv_bfloat162 t; t.x = a; t.y = b;
    return *reinterpret_cast<uint32_t*>(&t);
}
__device__ __forceinline__ void split2(float v, bf16& h, bf16& l) {
    h = __float2bfloat16_rn(v);
    l = __float2bfloat16_rn(v - __bfloat162float(h));
}
__device__ __forceinline__ void cpa16(uint32_t dst, const void* src) {
    asm volatile("cp.async.cg.shared.global [%0], [%1], 16;" :: "r"(dst), "l"(src));
}
#define CP_COMMIT() asm volatile("cp.async.commit_group;")

// ---------------------------------------------------------------------------
// K1: merged prep. Blocks [0,512): xsplit. Blocks [512,640): kv HMMA.
// ---------------------------------------------------------------------------
__global__ __launch_bounds__(256) void prep_kernel(const float* __restrict__ x,
                                                   const float* __restrict__ Wa) {
    if (blockIdx.x < 512) {
        const int base = blockIdx.x*256 + threadIdx.x;
#pragma unroll
        for (int q = 0; q < 8; ++q) {
            const int i = (q*131072 + base) * 4;
            float4 v = *(const float4*)&x[i];
            bf16 h0,l0,h1,l1,h2,l2,h3,l3;
            split2(v.x,h0,l0); split2(v.y,h1,l1);
            split2(v.z,h2,l2); split2(v.w,h3,l3);
            *(uint2*)&g_xh[i] = make_uint2(pk2(h0,h1), pk2(h2,h3));
            *(uint2*)&g_xl[i] = make_uint2(pk2(l0,l1), pk2(l2,l3));
        }
        return;
    }
    __shared__ __align__(16) bf16 sm[384*LDT];
    bf16* Ah = sm;
    bf16* Bh = sm + 128*LDT;
    const int bx  = blockIdx.x - 512;
    const int nt  = bx & 15;
    const int ks  = bx >> 4;
    const int tid = threadIdx.x;
    const int lane = tid & 31, wid = tid >> 5;
    const int mBase = (wid & 1) * 32, nBase = (wid >> 1) * 32;

    const int aR = (lane & 7) + ((lane >> 3) & 1)*8;
    const int aC = (lane >> 4)*8;
    const int bR = (lane & 7) + (lane >> 4)*8;
    const int bC = ((lane >> 3) & 1)*8;

    float acc[2][4][4];
#pragma unroll
    for (int mb = 0; mb < 2; ++mb)
#pragma unroll
        for (int nb = 0; nb < 4; ++nb)
#pragma unroll
            for (int q = 0; q < 4; ++q) acc[mb][nb][q] = 0.f;

    for (int k0 = ks*128; k0 < ks*128 + 128; k0 += 32) {
#pragma unroll
        for (int p = 0; p < 2; ++p) {
            const int idx = tid + p*256;
            const int row = idx >> 3, kq = (idx & 7) * 4;
            const int b = row >> 4, s = row & 15;
            float4 v = *(const float4*)&x[(b*Tn + s)*Cn + k0 + kq];
            bf16 hx,lx,hy,ly,hz,lz,hw,lw;
            split2(v.x,hx,lx); split2(v.y,hy,ly);
            split2(v.z,hz,lz); split2(v.w,hw,lw);
            *(uint2*)&Ah[row*LDT + kq]          = make_uint2(pk2(hx,hy), pk2(hz,hw));
            *(uint2*)&Ah[64*LDT + row*LDT + kq] = make_uint2(pk2(lx,ly), pk2(lz,lw));
        }
#pragma unroll
        for (int p = 0; p < 4; ++p) {
            const int idx = tid + p*256;
            const int row = idx >> 3, kq = (idx & 7) * 4;
            float4 v = *(const float4*)&Wa[(Cn + nt*128 + row)*Cn + k0 + kq];
            bf16 hx,lx,hy,ly,hz,lz,hw,lw;
            split2(v.x,hx,lx); split2(v.y,hy,ly);
            split2(v.z,hz,lz); split2(v.w,hw,lw);
            *(uint2*)&Bh[row*LDT + kq]           = make_uint2(pk2(hx,hy), pk2(hz,hw));
            *(uint2*)&Bh[128*LDT + row*LDT + kq] = make_uint2(pk2(lx,ly), pk2(lz,lw));
        }
        __syncthreads();
#pragma unroll
        for (int kk = 0; kk < 32; kk += 16) {
            uint32_t ah[2][4], al[2][4], bh2[2][4], bl2[2][4];
#pragma unroll
            for (int mb = 0; mb < 2; ++mb) {
                uint32_t ad = sptr(&Ah[(mBase + mb*16 + aR)*LDT + kk + aC]);
                ldsm4(ah[mb], ad);
                ldsm4(al[mb], ad + 64*LDT*2);
            }
#pragma unroll
            for (int q = 0; q < 2; ++q) {
                uint32_t bd = sptr(&Bh[(nBase + q*16 + bR)*LDT + kk + bC]);
                ldsm4(bh2[q], bd);
                ldsm4(bl2[q], bd + 128*LDT*2);
            }
#pragma unroll
            for (int mb = 0; mb < 2; ++mb)
#pragma unroll
                for (int nb = 0; nb < 4; ++nb) {
                    const uint32_t* bhp = &bh2[nb>>1][(nb&1)*2];
                    const uint32_t* blp = &bl2[nb>>1][(nb&1)*2];
                    mma16816(acc[mb][nb], ah[mb], bhp);
                    mma16816(acc[mb][nb], ah[mb], blp);
                    mma16816(acc[mb][nb], al[mb], bhp);
                }
        }
        __syncthreads();
    }
    const int g = lane >> 2, c2 = (lane & 3) * 2;
#pragma unroll
    for (int mb = 0; mb < 2; ++mb)
#pragma unroll
        for (int nb = 0; nb < 4; ++nb) {
            const int row = mBase + mb*16 + g;
            const int col = nt*128 + nBase + nb*8 + c2;
            *(float2*)&g_kvp[(ks*64 + row)*2048 + col] =
                make_float2(acc[mb][nb][0], acc[mb][nb][1]);
            *(float2*)&g_kvp[(ks*64 + row + 8)*2048 + col] =
                make_float2(acc[mb][nb][2], acc[mb][nb][3]);
        }
}

// ---------------------------------------------------------------------------
// K2: merged KQ / VP^T, reducing 8 kv partials inline (unchanged, proven).
// ---------------------------------------------------------------------------
__global__ __launch_bounds__(256) void kqvp_kernel(const float* __restrict__ Wa,
                                                   const float* __restrict__ Wp) {
    __shared__ float smem[12288];
    float (*Ws)[128] = (float(*)[128])smem;
    float (*ts)[64]  = (float(*)[64])(smem + 8192);
    const int ct  = blockIdx.x;
    const int h   = blockIdx.y;
    const int z   = blockIdx.z;
    const int tid = threadIdx.x;
    const int vcol = (z == 0) ? h*HDn : 1024 + h*HDn;

    if (z == 0) {
#pragma unroll
        for (int p = 0; p < 8; ++p) {
            const int idx = tid + p*256;
            const int d   = idx >> 5;
            const int f4  = (idx & 31) << 2;
            float4 v = *(const float4*)&Wa[(h*HDn + d)*Cn + ct*128 + f4];
            *(float4*)&Ws[d][f4] = v;
        }
    } else {
#pragma unroll
        for (int p = 0; p < 8; ++p) {
            const int idx = tid + p*256;
            const int j   = idx >> 4;
            const int f4  = (idx & 15) << 2;
            float4 v = *(const float4*)&Wp[(ct*128 + j)*Cn + h*HDn + f4];
            Ws[f4+0][j] = v.x; Ws[f4+1][j] = v.y;
            Ws[f4+2][j] = v.z; Ws[f4+3][j] = v.w;
        }
    }
#pragma unroll
    for (int p = 0; p < 4; ++p) {
        const int idx = tid + p*256;
        const int r   = idx >> 4;
        const int f4  = (idx & 15) << 2;
        float4 s = make_float4(0.f, 0.f, 0.f, 0.f);
#pragma unroll
        for (int ksp = 0; ksp < 8; ++ksp) {
            float4 v = *(const float4*)&g_kvp[(ksp*64 + r)*2048 + vcol + f4];
            s.x += v.x; s.y += v.y; s.z += v.z; s.w += v.w;
        }
        ts[f4+0][r] = s.x; ts[f4+1][r] = s.y;
        ts[f4+2][r] = s.z; ts[f4+3][r] = s.w;
    }
    __syncthreads();

    const int r0 = (tid >> 4) << 2;
    const int c0 = (tid & 15) << 3;
    float acc[4][8];
#pragma unroll
    for (int i = 0; i < 4; ++i)
#pragma unroll
        for (int j = 0; j < 8; ++j) acc[i][j] = 0.f;

#pragma unroll 8
    for (int d = 0; d < 64; ++d) {
        float4 a  = *(const float4*)&ts[d][r0];
        float4 b0 = *(const float4*)&Ws[d][c0];
        float4 b1 = *(const float4*)&Ws[d][c0+4];
        const float av[4] = {a.x, a.y, a.z, a.w};
        const float bv[8] = {b0.x,b0.y,b0.z,b0.w,b1.x,b1.y,b1.z,b1.w};
#pragma unroll
        for (int i = 0; i < 4; ++i)
#pragma unroll
            for (int j = 0; j < 8; ++j) acc[i][j] += av[i]*bv[j];
    }

    if (z == 0) {
#pragma unroll
        for (int i = 0; i < 4; ++i) {
            const int r = r0 + i, b = r >> 4, s = r & 15;
            const int base = (b*HKn + h*KSn + s)*Cn + ct*128 + c0;
            bf16 hi[8], lo[8];
#pragma unroll
            for (int j = 0; j < 8; ++j) split2(acc[i][j] * 0.125f, hi[j], lo[j]);
            *(uint4*)&g_KQh[base] = make_uint4(pk2(hi[0],hi[1]), pk2(hi[2],hi[3]),
                                               pk2(hi[4],hi[5]), pk2(hi[6],hi[7]));
            *(uint4*)&g_KQl[base] = make_uint4(pk2(lo[0],lo[1]), pk2(lo[2],lo[3]),
                                               pk2(lo[4],lo[5]), pk2(lo[6],lo[7]));
        }
    } else {
        __syncthreads();
        float* tp = smem;
#pragma unroll
        for (int i = 0; i < 4; ++i)
#pragma unroll
            for (int j = 0; j < 8; ++j)
                tp[(r0+i)*129 + c0 + j] = acc[i][j];
        __syncthreads();
#pragma unroll
        for (int p = 0; p < 2; ++p) {
            const int run = tid + p*256;
            const int bb  = run >> 7;
            const int j   = run & 127;
            bf16 hi[16], lo[16];
#pragma unroll
            for (int s = 0; s < 16; ++s)
                split2(tp[(bb*16 + s)*129 + j], hi[s], lo[s]);
            const int dst = (bb*Cn + ct*128 + j)*HKn + h*KSn;
            *(uint4*)&g_VPTh[dst]   = make_uint4(pk2(hi[0],hi[1]), pk2(hi[2],hi[3]),
                                                 pk2(hi[4],hi[5]), pk2(hi[6],hi[7]));
            *(uint4*)&g_VPTh[dst+8] = make_uint4(pk2(hi[8],hi[9]), pk2(hi[10],hi[11]),
                                                 pk2(hi[12],hi[13]), pk2(hi[14],hi[15]));
            *(uint4*)&g_VPTl[dst]   = make_uint4(pk2(lo[0],lo[1]), pk2(lo[2],lo[3]),
                                                 pk2(lo[4],lo[5]), pk2(lo[6],lo[7]));
            *(uint4*)&g_VPTl[dst+8] = make_uint4(pk2(lo[8],lo[9]), pk2(lo[10],lo[11]),
                                                 pk2(lo[12],lo[13]), pk2(lo[14],lo[15]));
        }
    }
}

// ---------------------------------------------------------------------------
// K3: logits = x @ KQ^T + fused softmax. CTA 64(t) x 64(hk = 4 heads),
// K=1024 in 16 chunks of 64, 3-stage cp.async, ONE sync per iteration.
// grid (4 n, 16 m, 4 b) = 256 CTAs, 256 thr; 110.6KB dyn smem, 2 CTA/SM.
// ---------------------------------------------------------------------------
#define AT_STG (256*LD2)      // bf16 elements per stage

__global__ __launch_bounds__(256) void attn_fused() {
    extern __shared__ __align__(16) bf16 sm[];    // 3*AT_STG
    const int tid  = threadIdx.x;
    const int nIdx = blockIdx.x;
    const int mIdx = blockIdx.y;
    const int b    = blockIdx.z;
    const int trow0 = b*Tn + mIdx*64;
    const int n0 = nIdx*64;
    const int lane = tid & 31, wid = tid >> 5;
    const int mW = (wid & 3) * 16, nW = (wid >> 2) * 32;

    const int aR = (lane & 7) + ((lane >> 3) & 1)*8;
    const int aC = (lane >> 4)*8;
    const int bR = (lane & 7) + (lane >> 4)*8;
    const int bC = ((lane >> 3) & 1)*8;

    float acc[4][4];
#pragma unroll
    for (int nb = 0; nb < 4; ++nb)
#pragma unroll
        for (int q = 0; q < 4; ++q) acc[nb][q] = 0.f;

    auto loadStage = [&](int s, int ch) {
        bf16* As = sm + s*AT_STG;
        bf16* Bs = As + 128*LD2;
        const int k0 = ch * 64;
#pragma unroll
        for (int p = 0; p < 4; ++p) {            // A: 128 rows (64 hi + 64 lo)
            const int idx = tid + p*256;
            const int r = idx >> 3;
            const int c = (idx & 7) * 8;
            const bf16* src = ((r & 64) ? g_xl : g_xh)
                            + (trow0 + (r & 63))*Cn + k0 + c;
            cpa16(sptr(&As[r*LD2 + c]), src);
        }
#pragma unroll
        for (int p = 0; p < 4; ++p) {            // B: 128 rows (64 hi + 64 lo)
            const int idx = tid + p*256;
            const int r = idx >> 3;
            const int c = (idx & 7) * 8;
            const bf16* src = ((r & 64) ? g_KQl : g_KQh)
                            + (b*HKn + n0 + (r & 63))*Cn + k0 + c;
            cpa16(sptr(&Bs[r*LD2 + c]), src);
        }
    };

    loadStage(0, 0); CP_COMMIT();
    loadStage(1, 1); CP_COMMIT();
    const int nIter = 16;
    int sIdx = 0;
    for (int it = 0; it < nIter; ++it) {
        if (it + 1 < nIter) asm volatile("cp.async.wait_group 1;" ::: "memory");
        else                asm volatile("cp.async.wait_group 0;" ::: "memory");
        __syncthreads();
        if (it + 2 < nIter) {
            int nxt = sIdx + 2; if (nxt >= 3) nxt -= 3;
            loadStage(nxt, it + 2);
            CP_COMMIT();
        }
        bf16* As = sm + sIdx*AT_STG;
        bf16* Bs = As + 128*LD2;
#pragma unroll
        for (int kk = 0; kk < 64; kk += 16) {
            uint32_t ah[4], al[4], bh2[2][4], bl2[2][4];
            uint32_t ad = sptr(&As[(mW + aR)*LD2 + kk + aC]);
            ldsm4(ah, ad);
            ldsm4(al, ad + 64*LD2*2);
#pragma unroll
            for (int q = 0; q < 2; ++q) {
                uint32_t bd = sptr(&Bs[(nW + q*16 + bR)*LD2 + kk + bC]);
                ldsm4(bh2[q], bd);
                ldsm4(bl2[q], bd + 64*LD2*2);
            }
#pragma unroll
            for (int nb = 0; nb < 4; ++nb) {
                const uint32_t* bhp = &bh2[nb>>1][(nb&1)*2];
                const uint32_t* blp = &bl2[nb>>1][(nb&1)*2];
                mma16816(acc[nb], ah, bhp);
                mma16816(acc[nb], ah, blp);
                mma16816(acc[nb], al, bhp);
            }
        }
        sIdx = (sIdx == 2) ? 0 : sIdx + 1;
    }
    __syncthreads();        // all compute reads done; reuse smem as logits

    // stage logits (64 x 64, stride 68 floats = 17.4KB)
    float* lg = (float*)sm;
    const int g = lane >> 2, c2 = (lane & 3) * 2;
#pragma unroll
    for (int nb = 0; nb < 4; ++nb) {
        const int row = mW + g;
        const int col = nW + nb*8 + c2;
        *(float2*)&lg[row*68 + col]     = make_float2(acc[nb][0], acc[nb][1]);
        *(float2*)&lg[(row+8)*68 + col] = make_float2(acc[nb][2], acc[nb][3]);
    }
    __syncthreads();

    // masked softmax: 64 rows x 4 heads = 256 groups, 1 per thread
    {
        const int tl = tid >> 2;
        const int hl = tid & 3;
        const int tb = mIdx*64 + tl;
        const int cnt = (tb + 1 < KSn) ? tb + 1 : KSn;
        const float* rowp = &lg[tl*68 + hl*16];
        float m = -3.0e38f;
#pragma unroll
        for (int s = 0; s < KSn; ++s) if (s < cnt) m = fmaxf(m, rowp[s]);
        float e[KSn]; float sum = 0.f;
#pragma unroll
        for (int s = 0; s < KSn; ++s) {
            float v = (s < cnt) ? expf(rowp[s] - m) : 0.f;
            e[s] = v; sum += v;
        }
        const float inv = 1.f / sum;
        bf16 hi[16], lo[16];
#pragma unroll
        for (int s = 0; s < KSn; ++s) split2(e[s]*inv, hi[s], lo[s]);
        const int base = (b*Tn + tb)*HKn + n0 + hl*16;
        *(uint4*)&g_wh[base]   = make_uint4(pk2(hi[0],hi[1]), pk2(hi[2],hi[3]),
                                            pk2(hi[4],hi[5]), pk2(hi[6],hi[7]));
        *(uint4*)&g_wh[base+8] = make_uint4(pk2(hi[8],hi[9]), pk2(hi[10],hi[11]),
                                            pk2(hi[12],hi[13]), pk2(hi[14],hi[15]));
        *(uint4*)&g_wl[base]   = make_uint4(pk2(lo[0],lo[1]), pk2(lo[2],lo[3]),
                                            pk2(lo[4],lo[5]), pk2(lo[6],lo[7]));
        *(uint4*)&g_wl[base+8] = make_uint4(pk2(lo[8],lo[9]), pk2(lo[10],lo[11]),
                                            pk2(lo[12],lo[13]), pk2(lo[14],lo[15]));
    }
}

// ---------------------------------------------------------------------------
// K4: out = w @ VP. CTA 64(t) x 64(j), K=256 in 4 chunks of 64, 3-stage
// cp.async, ONE sync per iteration. grid (16 j, 16 m, 4 b) = 1024 CTAs.
// ---------------------------------------------------------------------------
#define OT_STG (256*LD2)

__global__ __launch_bounds__(256) void out_mma(float* __restrict__ out) {
    extern __shared__ __align__(16) bf16 sm[];    // 3*OT_STG
    const int tid  = threadIdx.x;
    const int nIdx = blockIdx.x;
    const int mIdx = blockIdx.y;
    const int b    = blockIdx.z;
    const int trow0 = b*Tn + mIdx*64;
    const int j0 = nIdx*64;
    const int lane = tid & 31, wid = tid >> 5;
    const int mW = (wid & 3) * 16, nW = (wid >> 2) * 32;

    const int aR = (lane & 7) + ((lane >> 3) & 1)*8;
    const int aC = (lane >> 4)*8;
    const int bR = (lane & 7) + (lane >> 4)*8;
    const int bC = ((lane >> 3) & 1)*8;

    float acc[4][4];
#pragma unroll
    for (int nb = 0; nb < 4; ++nb)
#pragma unroll
        for (int q = 0; q < 4; ++q) acc[nb][q] = 0.f;

    auto loadStage = [&](int s, int ch) {
        bf16* As = sm + s*OT_STG;
        bf16* Bs = As + 128*LD2;
        const int k0 = ch * 64;
#pragma unroll
        for (int p = 0; p < 4; ++p) {            // A: w planes
            const int idx = tid + p*256;
            const int r = idx >> 3;
            const int c = (idx & 7) * 8;
            const bf16* src = ((r & 64) ? g_wl : g_wh)
                            + (trow0 + (r & 63))*HKn + k0 + c;
            cpa16(sptr(&As[r*LD2 + c]), src);
        }
#pragma unroll
        for (int p = 0; p < 4; ++p) {            // B: VPT planes
            const int idx = tid + p*256;
            const int r = idx >> 3;
            const int c = (idx & 7) * 8;
            const bf16* src = ((r & 64) ? g_VPTl : g_VPTh)
                            + (b*Cn + j0 + (r & 63))*HKn + k0 + c;
            cpa16(sptr(&Bs[r*LD2 + c]), src);
        }
    };

    loadStage(0, 0); CP_COMMIT();
    loadStage(1, 1); CP_COMMIT();
    const int nIter = 4;
    int sIdx = 0;
    for (int it = 0; it < nIter; ++it) {
        if (it + 1 < nIter) asm volatile("cp.async.wait_group 1;" ::: "memory");
        else                asm volatile("cp.async.wait_group 0;" ::: "memory");
        __syncthreads();
        if (it + 2 < nIter) {
            int nxt = sIdx + 2; if (nxt >= 3) nxt -= 3;
            loadStage(nxt, it + 2);
            CP_COMMIT();
        }
        bf16* As = sm + sIdx*OT_STG;
        bf16* Bs = As + 128*LD2;
#pragma unroll
        for (int kk = 0; kk < 64; kk += 16) {
            uint32_t ah[4], al[4], bh2[2][4], bl2[2][4];
            uint32_t ad = sptr(&As[(mW + aR)*LD2 + kk + aC]);
            ldsm4(ah, ad);
            ldsm4(al, ad + 64*LD2*2);
#pragma unroll
            for (int q = 0; q < 2; ++q) {
                uint32_t bd = sptr(&Bs[(nW + q*16 + bR)*LD2 + kk + bC]);
                ldsm4(bh2[q], bd);
                ldsm4(bl2[q], bd + 64*LD2*2);
            }
#pragma unroll
            for (int nb = 0; nb < 4; ++nb) {
                const uint32_t* bhp = &bh2[nb>>1][(nb&1)*2];
                const uint32_t* blp = &bl2[nb>>1][(nb&1)*2];
                mma16816(acc[nb], ah, bhp);
                mma16816(acc[nb], ah, blp);
                mma16816(acc[nb], al, bhp);
            }
        }
        sIdx = (sIdx == 2) ? 0 : sIdx + 1;
    }
    const int g = lane >> 2, c2 = (lane & 3) * 2;
#pragma unroll
    for (int nb = 0; nb < 4; ++nb) {
        const int row = trow0 + mW + g;
        const int col = j0 + nW + nb*8 + c2;
        *(float2*)&out[row*Cn + col]       = make_float2(acc[nb][0], acc[nb][1]);
        *(float2*)&out[(row + 8)*Cn + col] = make_float2(acc[nb][2], acc[nb][3]);
    }
}

// ---------------------------------------------------------------------------
extern "C" void kernel_launch(void* const* d_in, const int* in_sizes, int n_in,
                              void* d_out, int out_size) {
    const float* x  = (const float*)d_in[0];
    const float* Wa = (const float*)d_in[1];
    const float* Wp = (const float*)d_in[2];
    float* out = (float*)d_out;

    const int dynA = 3*AT_STG*sizeof(bf16);   // 110592 B
    const int dynO = 3*OT_STG*sizeof(bf16);
    cudaFuncSetAttribute(attn_fused, cudaFuncAttributeMaxDynamicSharedMemorySize, dynA);
    cudaFuncSetAttribute(out_mma,    cudaFuncAttributeMaxDynamicSharedMemorySize, dynO);

    prep_kernel <<<dim3(640),       256>>>(x, Wa);
    kqvp_kernel <<<dim3(8, 16, 2),  256>>>(Wa, Wp);
    attn_fused  <<<dim3(4, 16, 4),  256, dynA>>>();
    out_mma     <<<dim3(16, 16, 4), 256, dynO>>>(out);
}